// round 12
// baseline (speedup 1.0000x reference)
#include <cuda_runtime.h>
#include <cuda_bf16.h>
#include <math.h>
#include <stdint.h>

#define BB 2
#define TT 1024
#define DD 2048
#define HH 16
#define DHD 128
#define DHALF 1024

#define BM 128
#define BN 128
#define BKS 32

// EMA chunking: 64 chunks of 16 steps
#define NC 64
#define CL 16
#define BETA 0.9f
#define OMB  0.1f
#define BETA_L 0.1853020188851841f   // 0.9^16

// GEMM modes
#define M_Q 0
#define M_HDN 1
#define M_KV2 2
#define M_OUT 3

// ---------------- device scratch ----------------
__device__ float g_carryA[(size_t)BB*NC*DD];
__device__ float g_carryB[(size_t)BB*NC*DD];
__device__ float g_lampart[(size_t)BB*TT*8*3];   // per-block router partials

#define DECL_SPLIT(name, count) \
    __device__ __nv_bfloat16 name##_h[count]; \
    __device__ __nv_bfloat16 name##_l[count];

DECL_SPLIT(g_xs,   (size_t)BB*TT*DD)
DECL_SPLIT(g_wqs,  (size_t)DD*DD)
DECL_SPLIT(g_wks,  (size_t)DD*DD)
DECL_SPLIT(g_wvs,  (size_t)DD*DD)
DECL_SPLIT(g_wos,  (size_t)DD*DD)
DECL_SPLIT(g_rw1s, (size_t)DHALF*DD)
DECL_SPLIT(g_qs,   (size_t)BB*TT*DD)
DECL_SPLIT(g_fs,   (size_t)BB*TT*DD)
DECL_SPLIT(g_khs,  (size_t)BB*TT*DD)
DECL_SPLIT(g_vhs,  (size_t)BB*TT*DD)
DECL_SPLIT(g_aos,  (size_t)BB*TT*DD)

// ---------------- helpers ----------------
__device__ __forceinline__ void split2(float v, __nv_bfloat16* hi, __nv_bfloat16* lo) {
    __nv_bfloat16 h = __float2bfloat16(v);
    *hi = h;
    *lo = __float2bfloat16(v - __bfloat162float(h));
}
__device__ __forceinline__ uint32_t s2u(const void* p) {
    return (uint32_t)__cvta_generic_to_shared(p);
}
__device__ __forceinline__ void ldsm4(uint32_t* r, uint32_t addr) {
    asm volatile("ldmatrix.sync.aligned.m8n8.x4.shared.b16 {%0,%1,%2,%3}, [%4];"
                 : "=r"(r[0]), "=r"(r[1]), "=r"(r[2]), "=r"(r[3]) : "r"(addr));
}
__device__ __forceinline__ void ldsm2(uint32_t* r, uint32_t addr) {
    asm volatile("ldmatrix.sync.aligned.m8n8.x2.shared.b16 {%0,%1}, [%2];"
                 : "=r"(r[0]), "=r"(r[1]) : "r"(addr));
}
__device__ __forceinline__ void ldsm2t(uint32_t* r, uint32_t addr) {
    asm volatile("ldmatrix.sync.aligned.m8n8.x2.trans.shared.b16 {%0,%1}, [%2];"
                 : "=r"(r[0]), "=r"(r[1]) : "r"(addr));
}
__device__ __forceinline__ void mma16816(float* c, const uint32_t* a, const uint32_t* b) {
    asm volatile("mma.sync.aligned.m16n8k16.row.col.f32.bf16.bf16.f32 "
                 "{%0,%1,%2,%3}, {%4,%5,%6,%7}, {%8,%9}, {%0,%1,%2,%3};"
                 : "+f"(c[0]), "+f"(c[1]), "+f"(c[2]), "+f"(c[3])
                 : "r"(a[0]), "r"(a[1]), "r"(a[2]), "r"(a[3]), "r"(b[0]), "r"(b[1]));
}
__device__ __forceinline__ void cp16(uint32_t saddr, const void* g) {
    asm volatile("cp.async.cg.shared.global [%0], [%1], 16;" :: "r"(saddr), "l"(g));
}
__device__ __forceinline__ void cp_commit() {
    asm volatile("cp.async.commit_group;");
}
template<int N> __device__ __forceinline__ void cp_wait() {
    asm volatile("cp.async.wait_group %0;" :: "n"(N));
}
__device__ __forceinline__ uint32_t packb2(float lo_k, float hi_k) {
    __nv_bfloat162 t = __floats2bfloat162_rn(lo_k, hi_k);   // .x = low half
    return *reinterpret_cast<uint32_t*>(&t);
}

// split float4 -> hi uint2 (4 bf16) + lo uint2
__device__ __forceinline__ void split4v(float4 v, uint2* hi, uint2* lo) {
    __nv_bfloat16 h0 = __float2bfloat16(v.x);
    __nv_bfloat16 h1 = __float2bfloat16(v.y);
    __nv_bfloat16 h2 = __float2bfloat16(v.z);
    __nv_bfloat16 h3 = __float2bfloat16(v.w);
    float r0 = v.x - __bfloat162float(h0);
    float r1 = v.y - __bfloat162float(h1);
    float r2 = v.z - __bfloat162float(h2);
    float r3 = v.w - __bfloat162float(h3);
    __nv_bfloat162 p01; p01.x = h0; p01.y = h1;
    __nv_bfloat162 p23; p23.x = h2; p23.y = h3;
    hi->x = *reinterpret_cast<uint32_t*>(&p01);
    hi->y = *reinterpret_cast<uint32_t*>(&p23);
    lo->x = packb2(r0, r1);
    lo->y = packb2(r2, r3);
}

// ---------------- elementwise kernels (vectorized x4) ----------------
__global__ void split_v4_kernel(const float4* __restrict__ s,
                                uint2* __restrict__ hi, uint2* __restrict__ lo, int n4) {
    int i = blockIdx.x * blockDim.x + threadIdx.x;
    if (i >= n4) return;
    uint2 h, l;
    split4v(s[i], &h, &l);
    hi[i] = h; lo[i] = l;
}

__global__ void split4_v4_kernel(const float4* __restrict__ a, const float4* __restrict__ b,
                                 const float4* __restrict__ c, const float4* __restrict__ d,
                                 uint2* __restrict__ ah, uint2* __restrict__ al,
                                 uint2* __restrict__ bh, uint2* __restrict__ bl,
                                 uint2* __restrict__ ch, uint2* __restrict__ cl,
                                 uint2* __restrict__ dh, uint2* __restrict__ dl, int n4) {
    int i = blockIdx.x * blockDim.x + threadIdx.x;
    if (i >= n4) return;
    uint2 h, l;
    split4v(a[i], &h, &l); ah[i] = h; al[i] = l;
    split4v(b[i], &h, &l); bh[i] = h; bl[i] = l;
    split4v(c[i], &h, &l); ch[i] = h; cl[i] = l;
    split4v(d[i], &h, &l); dh[i] = h; dl[i] = l;
}

// ---- chunk-parallel EMA (NC=64 chunks of CL=16), float4-vectorized ----
// Fused: also emits the bf16 hi/lo split of x (saves a separate pass over x).
#define D4 (DD / 4)

__global__ void ema_chunk_split_v4(const float4* __restrict__ x4,
                                   float4* __restrict__ carryA4,
                                   uint2* __restrict__ xh4, uint2* __restrict__ xl4) {
    int idx = blockIdx.x * blockDim.x + threadIdx.x;
    if (idx >= BB * NC * D4) return;
    int c4 = idx % D4;
    int bc = idx / D4;
    int chunk = bc % NC;
    int b = bc / NC;
    size_t base = ((size_t)b * TT + (size_t)chunk * CL) * D4 + c4;
    float4 s = make_float4(0.f, 0.f, 0.f, 0.f);
    #pragma unroll
    for (int t = 0; t < CL; ++t) {
        float4 v = x4[base + (size_t)t * D4];
        s.x = BETA * s.x + OMB * v.x;
        s.y = BETA * s.y + OMB * v.y;
        s.z = BETA * s.z + OMB * v.z;
        s.w = BETA * s.w + OMB * v.w;
        uint2 h, l;
        split4v(v, &h, &l);
        xh4[base + (size_t)t * D4] = h;
        xl4[base + (size_t)t * D4] = l;
    }
    carryA4[idx] = s;
}

__global__ void ema_carry_v4(const float4* __restrict__ carryA4, float4* __restrict__ carryB4) {
    int idx = blockIdx.x * blockDim.x + threadIdx.x;
    if (idx >= BB * D4) return;
    int c4 = idx % D4;
    int b = idx / D4;
    float4 cin = make_float4(0.f, 0.f, 0.f, 0.f);
    #pragma unroll
    for (int j = 0; j < NC; ++j) {
        size_t off = ((size_t)b * NC + j) * D4 + c4;
        carryB4[off] = cin;
        float4 a = carryA4[off];
        cin.x = BETA_L * cin.x + a.x;
        cin.y = BETA_L * cin.y + a.y;
        cin.z = BETA_L * cin.z + a.z;
        cin.w = BETA_L * cin.w + a.w;
    }
}

// rescan + fuse + split, all in one pass
__global__ void ema_fuse_v4(const float4* __restrict__ x4, const float4* __restrict__ carryB4,
                            const float4* __restrict__ l34, const float* __restrict__ lam,
                            uint2* __restrict__ fh4, uint2* __restrict__ fl4) {
    int idx = blockIdx.x * blockDim.x + threadIdx.x;
    if (idx >= BB * NC * D4) return;
    int c4 = idx % D4;
    int bc = idx / D4;
    int chunk = bc % NC;
    int b = bc / NC;
    size_t base = ((size_t)b * TT + (size_t)chunk * CL) * D4 + c4;
    float4 s = carryB4[idx];
    float4 m = l34[(size_t)b * D4 + c4];
    int row0 = b * TT + chunk * CL;
    #pragma unroll
    for (int t = 0; t < CL; ++t) {
        float4 v = x4[base + (size_t)t * D4];
        s.x = BETA * s.x + OMB * v.x;
        s.y = BETA * s.y + OMB * v.y;
        s.z = BETA * s.z + OMB * v.z;
        s.w = BETA * s.w + OMB * v.w;
        int row = row0 + t;
        float a0 = lam[(size_t)row * 3 + 0];
        float a1 = lam[(size_t)row * 3 + 1];
        float a2 = lam[(size_t)row * 3 + 2];
        float4 f;
        f.x = a0 * v.x + a1 * s.x + a2 * m.x;
        f.y = a0 * v.y + a1 * s.y + a2 * m.y;
        f.z = a0 * v.z + a1 * s.z + a2 * m.z;
        f.w = a0 * v.w + a1 * s.w + a2 * m.w;
        uint2 h, l;
        split4v(f, &h, &l);
        fh4[base + (size_t)t * D4] = h;
        fl4[base + (size_t)t * D4] = l;
    }
}

// final router: sum 8 deterministic partials, add bias, softmax over 3
__global__ void router_final(const float* __restrict__ lampart,
                             const float* __restrict__ rb2,
                             float* __restrict__ lam) {
    int row = blockIdx.x * blockDim.x + threadIdx.x;
    if (row >= BB * TT) return;
    float z0 = rb2[0], z1 = rb2[1], z2 = rb2[2];
    #pragma unroll
    for (int p = 0; p < 8; ++p) {
        const float* q = lampart + ((size_t)row * 8 + p) * 3;
        z0 += q[0]; z1 += q[1]; z2 += q[2];
    }
    float m = fmaxf(z0, fmaxf(z1, z2));
    float e0 = expf(z0 - m), e1 = expf(z1 - m), e2 = expf(z2 - m);
    float inv = 1.0f / (e0 + e1 + e2);
    lam[(size_t)row * 3 + 0] = e0 * inv;
    lam[(size_t)row * 3 + 1] = e1 * inv;
    lam[(size_t)row * 3 + 2] = e2 * inv;
}

// ---------------- pipelined split-bf16 tensor-core GEMM ----------------
#define GEMM_SMEM (2 * 2 * BM * 40 * 2 * 2)

template<int MODE>
__global__ void __launch_bounds__(256, 2) mma_gemm(
    const __nv_bfloat16* __restrict__ Ahi, const __nv_bfloat16* __restrict__ Alo,
    const __nv_bfloat16* __restrict__ Bhi, const __nv_bfloat16* __restrict__ Blo,
    const __nv_bfloat16* __restrict__ B2hi, const __nv_bfloat16* __restrict__ B2lo,
    const float* __restrict__ bias,
    const float* __restrict__ rw2, float* __restrict__ lampart,
    float* __restrict__ Cf, float* __restrict__ Cf2,
    __nv_bfloat16* __restrict__ Chi, __nv_bfloat16* __restrict__ Clo,
    __nv_bfloat16* __restrict__ C2hi, __nv_bfloat16* __restrict__ C2lo,
    int M, int N, int K, int lda, int ldb)
{
    extern __shared__ __align__(16) char dynsmem[];
    __nv_bfloat16* sA = reinterpret_cast<__nv_bfloat16*>(dynsmem);
    __nv_bfloat16* sB = sA + 2 * 2 * BM * 40;

    int tid = threadIdx.x;
    int lane = tid & 31;
    int warp = tid >> 5;
    int wm = warp >> 2;
    int wn = warp & 3;
    int row0 = blockIdx.y * BM;

    int nb = N / BN;
    int which = 0;
    int bx = blockIdx.x;
    if (MODE == M_KV2) { which = bx / nb; bx -= which * nb; }
    int col0 = bx * BN;

    const __nv_bfloat16* Bh = (MODE == M_KV2 && which) ? B2hi : Bhi;
    const __nv_bfloat16* Bl = (MODE == M_KV2 && which) ? B2lo : Blo;

    float acc[4][4][4];
    #pragma unroll
    for (int a = 0; a < 4; ++a)
        #pragma unroll
        for (int b = 0; b < 4; ++b)
            #pragma unroll
            for (int c = 0; c < 4; ++c) acc[a][b][c] = 0.f;

    auto issue = [&](int k0, int st) {
        #pragma unroll
        for (int it = 0; it < 2; ++it) {
            int e = tid + it * 256;
            int r = e >> 2;
            int kc = (e & 3) * 8;
            size_t ao;
            if (MODE == M_OUT) {
                int gm = row0 + r, gk = k0 + kc;
                int b = gm >> 10, t = gm & (TT - 1);
                int h = gk >> 7, c = gk & (DHD - 1);
                ao = (((size_t)b * HH + h) * TT + t) * DHD + c;
            } else {
                ao = (size_t)(row0 + r) * lda + k0 + kc;
            }
            cp16(s2u(&sA[((st * 2 + 0) * BM + r) * 40 + kc]), Ahi + ao);
            cp16(s2u(&sA[((st * 2 + 1) * BM + r) * 40 + kc]), Alo + ao);
            size_t bo = (size_t)(col0 + r) * ldb + k0 + kc;
            cp16(s2u(&sB[((st * 2 + 0) * BM + r) * 40 + kc]), Bh + bo);
            cp16(s2u(&sB[((st * 2 + 1) * BM + r) * 40 + kc]), Bl + bo);
        }
    };

    int nIter = K / BKS;
    issue(0, 0);
    cp_commit();

    for (int i = 0; i < nIter; ++i) {
        int st = i & 1;
        if (i + 1 < nIter) {
            issue((i + 1) * BKS, (i + 1) & 1);
            cp_commit();
            cp_wait<1>();
        } else {
            cp_wait<0>();
        }
        __syncthreads();

        #pragma unroll
        for (int ks = 0; ks < BKS; ks += 16) {
            uint32_t afr[2][4][4];
            uint32_t bfr[2][4][2];
            #pragma unroll
            for (int mt = 0; mt < 4; ++mt) {
                int r = wm * 64 + mt * 16 + (lane & 15);
                int c = ks + (lane >> 4) * 8;
                ldsm4(afr[0][mt], s2u(&sA[((st * 2 + 0) * BM + r) * 40 + c]));
                ldsm4(afr[1][mt], s2u(&sA[((st * 2 + 1) * BM + r) * 40 + c]));
            }
            #pragma unroll
            for (int nt = 0; nt < 4; ++nt) {
                int r = wn * 32 + nt * 8 + (lane & 7);
                int c = ks + ((lane >> 3) & 1) * 8;
                ldsm2(bfr[0][nt], s2u(&sB[((st * 2 + 0) * BM + r) * 40 + c]));
                ldsm2(bfr[1][nt], s2u(&sB[((st * 2 + 1) * BM + r) * 40 + c]));
            }
            #pragma unroll
            for (int mt = 0; mt < 4; ++mt)
                #pragma unroll
                for (int nt = 0; nt < 4; ++nt) {
                    mma16816(acc[mt][nt], afr[0][mt], bfr[0][nt]);
                    mma16816(acc[mt][nt], afr[0][mt], bfr[1][nt]);
                    mma16816(acc[mt][nt], afr[1][mt], bfr[0][nt]);
                }
        }
        __syncthreads();
    }

    int g = lane >> 2, tg = lane & 3;

    if (MODE == M_HDN) {
        float zr[8][3];
        #pragma unroll
        for (int r = 0; r < 8; ++r)
            #pragma unroll
            for (int j = 0; j < 3; ++j) zr[r][j] = 0.f;

        #pragma unroll
        for (int mt = 0; mt < 4; ++mt)
            #pragma unroll
            for (int nt = 0; nt < 4; ++nt)
                #pragma unroll
                for (int i = 0; i < 4; ++i) {
                    int n = col0 + wn * 32 + nt * 8 + tg * 2 + (i & 1);
                    float v = acc[mt][nt][i] + bias[n];
                    v = v / (1.f + expf(-v));
                    int ri = mt * 2 + (i >> 1);
                    zr[ri][0] += v * rw2[n];
                    zr[ri][1] += v * rw2[DHALF + n];
                    zr[ri][2] += v * rw2[2 * DHALF + n];
                }
        #pragma unroll
        for (int r = 0; r < 8; ++r)
            #pragma unroll
            for (int j = 0; j < 3; ++j) {
                zr[r][j] += __shfl_xor_sync(0xffffffffu, zr[r][j], 1);
                zr[r][j] += __shfl_xor_sync(0xffffffffu, zr[r][j], 2);
            }
        __shared__ float zsm[4][128][3];
        if (tg == 0) {
            #pragma unroll
            for (int r = 0; r < 8; ++r) {
                int lr = wm * 64 + (r >> 1) * 16 + g + (r & 1) * 8;
                #pragma unroll
                for (int j = 0; j < 3; ++j) zsm[wn][lr][j] = zr[r][j];
            }
        }
        __syncthreads();
        if (tid < 128) {
            int gm = row0 + tid;
            float* dst = lampart + ((size_t)gm * 8 + blockIdx.x) * 3;
            #pragma unroll
            for (int j = 0; j < 3; ++j)
                dst[j] = zsm[0][tid][j] + zsm[1][tid][j] + zsm[2][tid][j] + zsm[3][tid][j];
        }
        return;
    }

    #pragma unroll
    for (int mt = 0; mt < 4; ++mt)
        #pragma unroll
        for (int nt = 0; nt < 4; ++nt)
            #pragma unroll
            for (int i = 0; i < 4; ++i) {
                int m = row0 + wm * 64 + mt * 16 + g + (i >> 1) * 8;
                int n = col0 + wn * 32 + nt * 8 + tg * 2 + (i & 1);
                float v = acc[mt][nt][i];
                if (MODE == M_Q) {
                    size_t idx = (size_t)m * N + n;
                    split2(v, &Chi[idx], &Clo[idx]);
                } else if (MODE == M_KV2) {
                    int b = m >> 10, t = m & (TT - 1);
                    int h = n >> 7, c = n & (DHD - 1);
                    size_t idx = (((size_t)b * HH + h) * TT + t) * DHD + c;
                    if (which == 0) {
                        Cf[idx] = v;
                        split2(v, &Chi[idx], &Clo[idx]);
                    } else {
                        Cf2[idx] = v;
                        split2(v, &C2hi[idx], &C2lo[idx]);
                    }
                } else {
                    Cf[(size_t)m * N + n] = v;
                }
            }
}

// ---------------- flash attention ----------------
// Q hi-only; PV drops pl term. Paired q-tiles: CTA x handles (NQB-1-x) then (x),
// giving every CTA exactly NQB+1 tile-iterations -> one balanced wave of 128 CTAs.
#define FL_PITCH 136
#define FL_TILE  (128 * FL_PITCH)
#define FLASH_SMEM (5 * FL_TILE * 2)
#define NQB (TT / 128)

__global__ void __launch_bounds__(256) flash_kernel(
    const __nv_bfloat16* __restrict__ qh_,
    const __nv_bfloat16* __restrict__ khh, const __nv_bfloat16* __restrict__ khl,
    const __nv_bfloat16* __restrict__ vhh, const __nv_bfloat16* __restrict__ vhl,
    __nv_bfloat16* __restrict__ aoh, __nv_bfloat16* __restrict__ aol,
    float scale)
{
    extern __shared__ __align__(16) char fsm[];
    __nv_bfloat16* sQh = reinterpret_cast<__nv_bfloat16*>(fsm);
    __nv_bfloat16* sKh = sQh + FL_TILE;
    __nv_bfloat16* sKl = sKh + FL_TILE;
    __nv_bfloat16* sVh = sKl + FL_TILE;
    __nv_bfloat16* sVl = sVh + FL_TILE;

    int tid = threadIdx.x;
    int lane = tid & 31;
    int wid = tid >> 5;
    int g = lane >> 2, tg = lane & 3;

    int z = blockIdx.y;
    int b = z / HH, h = z % HH;

    const __nv_bfloat16* qbh = qh_ + (size_t)b * TT * DD + (size_t)h * DHD;
    const __nv_bfloat16* kbh = khh + (size_t)z * TT * DHD;
    const __nv_bfloat16* kbl = khl + (size_t)z * TT * DHD;
    const __nv_bfloat16* vbh = vhh + (size_t)z * TT * DHD;
    const __nv_bfloat16* vbl = vhl + (size_t)z * TT * DHD;

    auto loadK = [&](int kb2) {
        for (int e = tid; e < 128 * 16; e += 256) {
            int r = e >> 4, c8 = (e & 15) * 8;
            size_t go = (size_t)(kb2 * 128 + r) * DHD + c8;
            cp16(s2u(&sKh[r * FL_PITCH + c8]), kbh + go);
            cp16(s2u(&sKl[r * FL_PITCH + c8]), kbl + go);
        }
    };
    auto loadV = [&](int kb2) {
        for (int e = tid; e < 128 * 16; e += 256) {
            int r = e >> 4, c8 = (e & 15) * 8;
            size_t go = (size_t)(kb2 * 128 + r) * DHD + c8;
            cp16(s2u(&sVh[r * FL_PITCH + c8]), vbh + go);
            cp16(s2u(&sVl[r * FL_PITCH + c8]), vbl + go);
        }
    };

    #pragma unroll
    for (int rep = 0; rep < 2; ++rep) {
        int qb = rep == 0 ? (NQB - 1 - blockIdx.x) : blockIdx.x;  // heavy tile first
        int row0 = qb * 128;

        __syncthreads();   // all warps past previous rep's smem reads
        for (int e = tid; e < 128 * 16; e += 256) {
            int r = e >> 4, c8 = (e & 15) * 8;
            *reinterpret_cast<uint4*>(&sQh[r * FL_PITCH + c8]) =
                *reinterpret_cast<const uint4*>(qbh + (size_t)(row0 + r) * DD + c8);
        }
        loadK(0); cp_commit();
        loadV(0); cp_commit();

        float accO[16][4];
        #pragma unroll
        for (int i = 0; i < 16; ++i)
            #pragma unroll
            for (int j = 0; j < 4; ++j) accO[i][j] = 0.f;
        float mrun0 = -INFINITY, mrun1 = -INFINITY;
        float lrun0 = 0.f, lrun1 = 0.f;

        for (int kb = 0; kb <= qb; ++kb) {
            cp_wait<1>();
            __syncthreads();

            // ---- S = Qh (Kh + Kl)^T ----
            float S[16][4];
            #pragma unroll
            for (int i = 0; i < 16; ++i)
                #pragma unroll
                for (int j = 0; j < 4; ++j) S[i][j] = 0.f;

            #pragma unroll
            for (int ks = 0; ks < 8; ++ks) {
                uint32_t qf[4];
                {
                    int r = wid * 16 + (lane & 15);
                    int c = ks * 16 + (lane >> 4) * 8;
                    ldsm4(qf, s2u(&sQh[r * FL_PITCH + c]));
                }
                #pragma unroll
                for (int nt = 0; nt < 16; ++nt) {
                    uint32_t bh[2], bl[2];
                    int r = nt * 8 + (lane & 7);
                    int c = ks * 16 + ((lane >> 3) & 1) * 8;
                    ldsm2(bh, s2u(&sKh[r * FL_PITCH + c]));
                    ldsm2(bl, s2u(&sKl[r * FL_PITCH + c]));
                    mma16816(S[nt], qf, bh);
                    mma16816(S[nt], qf, bl);
                }
            }
            __syncthreads();
            if (kb < qb) { loadK(kb + 1); cp_commit(); }

            // ---- scale + mask + online softmax ----
            bool diag = (kb == qb);
            #pragma unroll
            for (int nt = 0; nt < 16; ++nt)
                #pragma unroll
                for (int j = 0; j < 4; ++j) {
                    float v = S[nt][j] * scale;
                    if (diag) {
                        int n = nt * 8 + tg * 2 + (j & 1);
                        int m = wid * 16 + g + ((j >> 1) ? 8 : 0);
                        if (n > m) v = -INFINITY;
                    }
                    S[nt][j] = v;
                }

            float mx0 = -INFINITY, mx1 = -INFINITY;
            #pragma unroll
            for (int nt = 0; nt < 16; ++nt) {
                mx0 = fmaxf(mx0, fmaxf(S[nt][0], S[nt][1]));
                mx1 = fmaxf(mx1, fmaxf(S[nt][2], S[nt][3]));
            }
            mx0 = fmaxf(mx0, __shfl_xor_sync(0xffffffffu, mx0, 1));
            mx0 = fmaxf(mx0, __shfl_xor_sync(0xffffffffu, mx0, 2));
            mx1 = fmaxf(mx1, __shfl_xor_sync(0xffffffffu, mx1, 1));
            mx1 = fmaxf(mx1, __shfl_xor_sync(0xffffffffu, mx1, 2));

            float mn0 = fmaxf(mrun0, mx0);
            float mn1 = fmaxf(mrun1, mx1);
            float al0 = expf(mrun0 - mn0);
            float al1 = expf(mrun1 - mn1);
            mrun0 = mn0; mrun1 = mn1;

            float ls0 = 0.f, ls1 = 0.f;
            #pragma unroll
            for (int nt = 0; nt < 16; ++nt) {
                float e0 = expf(S[nt][0] - mn0);
                float e1 = expf(S[nt][1] - mn0);
                float e2 = expf(S[nt][2] - mn1);
                float e3 = expf(S[nt][3] - mn1);
                S[nt][0] = e0; S[nt][1] = e1; S[nt][2] = e2; S[nt][3] = e3;
                ls0 += e0 + e1;
                ls1 += e2 + e3;
            }
            lrun0 = lrun0 * al0 + ls0;
            lrun1 = lrun1 * al1 + ls1;

            #pragma unroll
            for (int nt = 0; nt < 16; ++nt) {
                accO[nt][0] *= al0; accO[nt][1] *= al0;
                accO[nt][2] *= al1; accO[nt][3] *= al1;
            }

            if (kb < qb) cp_wait<1>(); else cp_wait<0>();
            __syncthreads();

            // ---- O += Ph (Vh + Vl) ----
            #pragma unroll
            for (int kk = 0; kk < 8; ++kk) {
                uint32_t ph[4];
                ph[0] = packb2(S[2 * kk][0],     S[2 * kk][1]);
                ph[1] = packb2(S[2 * kk][2],     S[2 * kk][3]);
                ph[2] = packb2(S[2 * kk + 1][0], S[2 * kk + 1][1]);
                ph[3] = packb2(S[2 * kk + 1][2], S[2 * kk + 1][3]);
                #pragma unroll
                for (int ndt = 0; ndt < 16; ++ndt) {
                    uint32_t vh2[2], vl2[2];
                    int rr = kk * 16 + (lane & 15);
                    int cc = ndt * 8;
                    ldsm2t(vh2, s2u(&sVh[rr * FL_PITCH + cc]));
                    ldsm2t(vl2, s2u(&sVl[rr * FL_PITCH + cc]));
                    mma16816(accO[ndt], ph, vh2);
                    mma16816(accO[ndt], ph, vl2);
                }
            }
            __syncthreads();
            if (kb < qb) { loadV(kb + 1); cp_commit(); }
        }

        lrun0 += __shfl_xor_sync(0xffffffffu, lrun0, 1);
        lrun0 += __shfl_xor_sync(0xffffffffu, lrun0, 2);
        lrun1 += __shfl_xor_sync(0xffffffffu, lrun1, 1);
        lrun1 += __shfl_xor_sync(0xffffffffu, lrun1, 2);
        float inv0 = 1.0f / lrun0;
        float inv1 = 1.0f / lrun1;

        size_t obase = (size_t)z * TT * DHD;
        #pragma unroll
        for (int ndt = 0; ndt < 16; ++ndt)
            #pragma unroll
            for (int j = 0; j < 4; ++j) {
                int m = row0 + wid * 16 + g + ((j >> 1) ? 8 : 0);
                int n = ndt * 8 + tg * 2 + (j & 1);
                float v = accO[ndt][j] * ((j >> 1) ? inv1 : inv0);
                size_t idx = obase + (size_t)m * DHD + n;
                split2(v, &aoh[idx], &aol[idx]);
            }
    }
}

// ---------------- host ----------------
#define SYMADDR(var, sym) cudaGetSymbolAddress((void**)&var, sym)

extern "C" void kernel_launch(void* const* d_in, const int* in_sizes, int n_in,
                              void* d_out, int out_size) {
    const float* x   = (const float*)d_in[0];
    const float* l3  = (const float*)d_in[1];
    const float* wq  = (const float*)d_in[2];
    const float* wk  = (const float*)d_in[3];
    const float* wv  = (const float*)d_in[4];
    const float* wo  = (const float*)d_in[5];
    const float* rw1 = (const float*)d_in[6];
    const float* rb1 = (const float*)d_in[7];
    const float* rw2 = (const float*)d_in[8];
    const float* rb2 = (const float*)d_in[9];

    float* out     = (float*)d_out;
    float* kh_out  = out    + (size_t)BB * TT * DD;
    float* vh_out  = kh_out + (size_t)BB * TT * DD;
    float* lam_out = vh_out + (size_t)BB * TT * DD;

    float *carryA, *carryB, *lampart;
    SYMADDR(carryA, g_carryA); SYMADDR(carryB, g_carryB);
    SYMADDR(lampart, g_lampart);

    __nv_bfloat16 *xs_h,*xs_l, *wqs_h,*wqs_l, *wks_h,*wks_l, *wvs_h,*wvs_l,
                  *wos_h,*wos_l, *rw1s_h,*rw1s_l, *qs_h,*qs_l, *fs_h,*fs_l,
                  *khs_h,*khs_l, *vhs_h,*vhs_l, *aos_h,*aos_l;
    SYMADDR(xs_h, g_xs_h);     SYMADDR(xs_l, g_xs_l);
    SYMADDR(wqs_h, g_wqs_h);   SYMADDR(wqs_l, g_wqs_l);
    SYMADDR(wks_h, g_wks_h);   SYMADDR(wks_l, g_wks_l);
    SYMADDR(wvs_h, g_wvs_h);   SYMADDR(wvs_l, g_wvs_l);
    SYMADDR(wos_h, g_wos_h);   SYMADDR(wos_l, g_wos_l);
    SYMADDR(rw1s_h, g_rw1s_h); SYMADDR(rw1s_l, g_rw1s_l);
    SYMADDR(qs_h, g_qs_h);     SYMADDR(qs_l, g_qs_l);
    SYMADDR(fs_h, g_fs_h);     SYMADDR(fs_l, g_fs_l);
    SYMADDR(khs_h, g_khs_h);   SYMADDR(khs_l, g_khs_l);
    SYMADDR(vhs_h, g_vhs_h);   SYMADDR(vhs_l, g_vhs_l);
    SYMADDR(aos_h, g_aos_h);   SYMADDR(aos_l, g_aos_l);

    const int M = BB * TT;
    const float scale = 1.0f / sqrtf((float)DHD);
    const int NW4 = (int)((size_t)DD * DD / 4);

    cudaFuncSetAttribute(mma_gemm<M_Q>,   cudaFuncAttributeMaxDynamicSharedMemorySize, GEMM_SMEM);
    cudaFuncSetAttribute(mma_gemm<M_HDN>, cudaFuncAttributeMaxDynamicSharedMemorySize, GEMM_SMEM);
    cudaFuncSetAttribute(mma_gemm<M_KV2>, cudaFuncAttributeMaxDynamicSharedMemorySize, GEMM_SMEM);
    cudaFuncSetAttribute(mma_gemm<M_OUT>, cudaFuncAttributeMaxDynamicSharedMemorySize, GEMM_SMEM);
    cudaFuncSetAttribute(flash_kernel,    cudaFuncAttributeMaxDynamicSharedMemorySize, FLASH_SMEM);

    // weight splits (vectorized x4)
    split4_v4_kernel<<<(NW4 + 255) / 256, 256>>>(
        (const float4*)wq, (const float4*)wk, (const float4*)wv, (const float4*)wo,
        (uint2*)wqs_h, (uint2*)wqs_l, (uint2*)wks_h, (uint2*)wks_l,
        (uint2*)wvs_h, (uint2*)wvs_l, (uint2*)wos_h, (uint2*)wos_l, NW4);
    split_v4_kernel<<<(NW4 / 2 + 255) / 256, 256>>>(
        (const float4*)rw1, (uint2*)rw1s_h, (uint2*)rw1s_l, NW4 / 2);

    // EMA chunk scan fused with x split; then carries
    ema_chunk_split_v4<<<(BB * NC * D4 + 255) / 256, 256>>>(
        (const float4*)x, (float4*)carryA, (uint2*)xs_h, (uint2*)xs_l);
    ema_carry_v4<<<(BB * D4 + 255) / 256, 256>>>((const float4*)carryA, (float4*)carryB);

    // q = x @ wq^T
    mma_gemm<M_Q><<<dim3(DD / BN, M / BM), 256, GEMM_SMEM>>>(
        xs_h, xs_l, wqs_h, wqs_l, nullptr, nullptr, nullptr, nullptr, nullptr,
        nullptr, nullptr, qs_h, qs_l, nullptr, nullptr, M, DD, DD, DD, DD);

    // hdn + router partials fused
    mma_gemm<M_HDN><<<dim3(DHALF / BN, M / BM), 256, GEMM_SMEM>>>(
        qs_h, qs_l, rw1s_h, rw1s_l, nullptr, nullptr, rb1, rw2, lampart,
        nullptr, nullptr, nullptr, nullptr, nullptr, nullptr, M, DHALF, DD, DD, DD);

    // lam = softmax(sum partials + rb2)
    router_final<<<(M + 255) / 256, 256>>>(lampart, rb2, lam_out);

    // EMA rescan + fuse + split (single pass)
    ema_fuse_v4<<<(BB * NC * D4 + 255) / 256, 256>>>(
        (const float4*)x, (const float4*)carryB, (const float4*)l3, lam_out,
        (uint2*)fs_h, (uint2*)fs_l);

    // kh + vh in ONE launch
    mma_gemm<M_KV2><<<dim3(2 * DD / BN, M / BM), 256, GEMM_SMEM>>>(
        fs_h, fs_l, wks_h, wks_l, wvs_h, wvs_l, nullptr, nullptr, nullptr,
        kh_out, vh_out, khs_h, khs_l, vhs_h, vhs_l, M, DD, DD, DD, DD);

    // flash attention (paired q-tiles, balanced single wave)
    flash_kernel<<<dim3(NQB / 2, BB * HH), 256, FLASH_SMEM>>>(
        qs_h, khs_h, khs_l, vhs_h, vhs_l, aos_h, aos_l, scale);

    // out = concat_heads(ao) @ wo^T
    mma_gemm<M_OUT><<<dim3(DD / BN, M / BM), 256, GEMM_SMEM>>>(
        aos_h, aos_l, wos_h, wos_l, nullptr, nullptr, nullptr, nullptr, nullptr,
        out, nullptr, nullptr, nullptr, nullptr, nullptr, M, DD, DD, DD, DD);
}

// round 13
// speedup vs baseline: 1.4741x; 1.4741x over previous
#include <cuda_runtime.h>
#include <cuda_bf16.h>
#include <math.h>
#include <stdint.h>

#define BB 2
#define TT 1024
#define DD 2048
#define HH 16
#define DHD 128
#define DHALF 1024

#define BM 128
#define BN 128
#define BKS 32

// EMA chunking: 64 chunks of 16 steps
#define NC 64
#define CL 16
#define BETA 0.9f
#define OMB  0.1f
#define BETA_L 0.1853020188851841f   // 0.9^16

// GEMM modes
#define M_Q 0
#define M_HDN 1
#define M_KV2 2
#define M_OUT 3

// ---------------- device scratch ----------------
__device__ float g_carryA[(size_t)BB*NC*DD];
__device__ float g_carryB[(size_t)BB*NC*DD];
__device__ float g_lampart[(size_t)BB*TT*8*3];   // per-block router partials

#define DECL_SPLIT(name, count) \
    __device__ __nv_bfloat16 name##_h[count]; \
    __device__ __nv_bfloat16 name##_l[count];

DECL_SPLIT(g_xs,   (size_t)BB*TT*DD)
DECL_SPLIT(g_wqs,  (size_t)DD*DD)
DECL_SPLIT(g_wks,  (size_t)DD*DD)
DECL_SPLIT(g_wvs,  (size_t)DD*DD)
DECL_SPLIT(g_wos,  (size_t)DD*DD)
DECL_SPLIT(g_rw1s, (size_t)DHALF*DD)
DECL_SPLIT(g_qs,   (size_t)BB*TT*DD)
DECL_SPLIT(g_fs,   (size_t)BB*TT*DD)
DECL_SPLIT(g_khs,  (size_t)BB*TT*DD)
DECL_SPLIT(g_vhs,  (size_t)BB*TT*DD)
DECL_SPLIT(g_aos,  (size_t)BB*TT*DD)

// ---------------- helpers ----------------
__device__ __forceinline__ void split2(float v, __nv_bfloat16* hi, __nv_bfloat16* lo) {
    __nv_bfloat16 h = __float2bfloat16(v);
    *hi = h;
    *lo = __float2bfloat16(v - __bfloat162float(h));
}
__device__ __forceinline__ uint32_t s2u(const void* p) {
    return (uint32_t)__cvta_generic_to_shared(p);
}
__device__ __forceinline__ void ldsm4(uint32_t* r, uint32_t addr) {
    asm volatile("ldmatrix.sync.aligned.m8n8.x4.shared.b16 {%0,%1,%2,%3}, [%4];"
                 : "=r"(r[0]), "=r"(r[1]), "=r"(r[2]), "=r"(r[3]) : "r"(addr));
}
__device__ __forceinline__ void ldsm2(uint32_t* r, uint32_t addr) {
    asm volatile("ldmatrix.sync.aligned.m8n8.x2.shared.b16 {%0,%1}, [%2];"
                 : "=r"(r[0]), "=r"(r[1]) : "r"(addr));
}
__device__ __forceinline__ void ldsm2t(uint32_t* r, uint32_t addr) {
    asm volatile("ldmatrix.sync.aligned.m8n8.x2.trans.shared.b16 {%0,%1}, [%2];"
                 : "=r"(r[0]), "=r"(r[1]) : "r"(addr));
}
__device__ __forceinline__ void mma16816(float* c, const uint32_t* a, const uint32_t* b) {
    asm volatile("mma.sync.aligned.m16n8k16.row.col.f32.bf16.bf16.f32 "
                 "{%0,%1,%2,%3}, {%4,%5,%6,%7}, {%8,%9}, {%0,%1,%2,%3};"
                 : "+f"(c[0]), "+f"(c[1]), "+f"(c[2]), "+f"(c[3])
                 : "r"(a[0]), "r"(a[1]), "r"(a[2]), "r"(a[3]), "r"(b[0]), "r"(b[1]));
}
__device__ __forceinline__ void cp16(uint32_t saddr, const void* g) {
    asm volatile("cp.async.cg.shared.global [%0], [%1], 16;" :: "r"(saddr), "l"(g));
}
__device__ __forceinline__ void cp_commit() {
    asm volatile("cp.async.commit_group;");
}
template<int N> __device__ __forceinline__ void cp_wait() {
    asm volatile("cp.async.wait_group %0;" :: "n"(N));
}
__device__ __forceinline__ uint32_t packb2(float lo_k, float hi_k) {
    __nv_bfloat162 t = __floats2bfloat162_rn(lo_k, hi_k);   // .x = low half
    return *reinterpret_cast<uint32_t*>(&t);
}

// split float4 -> hi uint2 (4 bf16) + lo uint2
__device__ __forceinline__ void split4v(float4 v, uint2* hi, uint2* lo) {
    __nv_bfloat16 h0 = __float2bfloat16(v.x);
    __nv_bfloat16 h1 = __float2bfloat16(v.y);
    __nv_bfloat16 h2 = __float2bfloat16(v.z);
    __nv_bfloat16 h3 = __float2bfloat16(v.w);
    float r0 = v.x - __bfloat162float(h0);
    float r1 = v.y - __bfloat162float(h1);
    float r2 = v.z - __bfloat162float(h2);
    float r3 = v.w - __bfloat162float(h3);
    __nv_bfloat162 p01; p01.x = h0; p01.y = h1;
    __nv_bfloat162 p23; p23.x = h2; p23.y = h3;
    hi->x = *reinterpret_cast<uint32_t*>(&p01);
    hi->y = *reinterpret_cast<uint32_t*>(&p23);
    lo->x = packb2(r0, r1);
    lo->y = packb2(r2, r3);
}

// ---------------- elementwise kernels (vectorized x4) ----------------
__global__ void split_v4_kernel(const float4* __restrict__ s,
                                uint2* __restrict__ hi, uint2* __restrict__ lo, int n4) {
    int i = blockIdx.x * blockDim.x + threadIdx.x;
    if (i >= n4) return;
    uint2 h, l;
    split4v(s[i], &h, &l);
    hi[i] = h; lo[i] = l;
}

__global__ void split4_v4_kernel(const float4* __restrict__ a, const float4* __restrict__ b,
                                 const float4* __restrict__ c, const float4* __restrict__ d,
                                 uint2* __restrict__ ah, uint2* __restrict__ al,
                                 uint2* __restrict__ bh, uint2* __restrict__ bl,
                                 uint2* __restrict__ ch, uint2* __restrict__ cl,
                                 uint2* __restrict__ dh, uint2* __restrict__ dl, int n4) {
    int i = blockIdx.x * blockDim.x + threadIdx.x;
    if (i >= n4) return;
    uint2 h, l;
    split4v(a[i], &h, &l); ah[i] = h; al[i] = l;
    split4v(b[i], &h, &l); bh[i] = h; bl[i] = l;
    split4v(c[i], &h, &l); ch[i] = h; cl[i] = l;
    split4v(d[i], &h, &l); dh[i] = h; dl[i] = l;
}

// ---- chunk-parallel EMA (NC=64 chunks of CL=16), float4-vectorized ----
// Fused: also emits the bf16 hi/lo split of x (saves a separate pass over x).
#define D4 (DD / 4)

__global__ void ema_chunk_split_v4(const float4* __restrict__ x4,
                                   float4* __restrict__ carryA4,
                                   uint2* __restrict__ xh4, uint2* __restrict__ xl4) {
    int idx = blockIdx.x * blockDim.x + threadIdx.x;
    if (idx >= BB * NC * D4) return;
    int c4 = idx % D4;
    int bc = idx / D4;
    int chunk = bc % NC;
    int b = bc / NC;
    size_t base = ((size_t)b * TT + (size_t)chunk * CL) * D4 + c4;
    float4 s = make_float4(0.f, 0.f, 0.f, 0.f);
    #pragma unroll
    for (int t = 0; t < CL; ++t) {
        float4 v = x4[base + (size_t)t * D4];
        s.x = BETA * s.x + OMB * v.x;
        s.y = BETA * s.y + OMB * v.y;
        s.z = BETA * s.z + OMB * v.z;
        s.w = BETA * s.w + OMB * v.w;
        uint2 h, l;
        split4v(v, &h, &l);
        xh4[base + (size_t)t * D4] = h;
        xl4[base + (size_t)t * D4] = l;
    }
    carryA4[idx] = s;
}

__global__ void ema_carry_v4(const float4* __restrict__ carryA4, float4* __restrict__ carryB4) {
    int idx = blockIdx.x * blockDim.x + threadIdx.x;
    if (idx >= BB * D4) return;
    int c4 = idx % D4;
    int b = idx / D4;
    float4 cin = make_float4(0.f, 0.f, 0.f, 0.f);
    #pragma unroll
    for (int j = 0; j < NC; ++j) {
        size_t off = ((size_t)b * NC + j) * D4 + c4;
        carryB4[off] = cin;
        float4 a = carryA4[off];
        cin.x = BETA_L * cin.x + a.x;
        cin.y = BETA_L * cin.y + a.y;
        cin.z = BETA_L * cin.z + a.z;
        cin.w = BETA_L * cin.w + a.w;
    }
}

// rescan + fuse + split, all in one pass
__global__ void ema_fuse_v4(const float4* __restrict__ x4, const float4* __restrict__ carryB4,
                            const float4* __restrict__ l34, const float* __restrict__ lam,
                            uint2* __restrict__ fh4, uint2* __restrict__ fl4) {
    int idx = blockIdx.x * blockDim.x + threadIdx.x;
    if (idx >= BB * NC * D4) return;
    int c4 = idx % D4;
    int bc = idx / D4;
    int chunk = bc % NC;
    int b = bc / NC;
    size_t base = ((size_t)b * TT + (size_t)chunk * CL) * D4 + c4;
    float4 s = carryB4[idx];
    float4 m = l34[(size_t)b * D4 + c4];
    int row0 = b * TT + chunk * CL;
    #pragma unroll
    for (int t = 0; t < CL; ++t) {
        float4 v = x4[base + (size_t)t * D4];
        s.x = BETA * s.x + OMB * v.x;
        s.y = BETA * s.y + OMB * v.y;
        s.z = BETA * s.z + OMB * v.z;
        s.w = BETA * s.w + OMB * v.w;
        int row = row0 + t;
        float a0 = lam[(size_t)row * 3 + 0];
        float a1 = lam[(size_t)row * 3 + 1];
        float a2 = lam[(size_t)row * 3 + 2];
        float4 f;
        f.x = a0 * v.x + a1 * s.x + a2 * m.x;
        f.y = a0 * v.y + a1 * s.y + a2 * m.y;
        f.z = a0 * v.z + a1 * s.z + a2 * m.z;
        f.w = a0 * v.w + a1 * s.w + a2 * m.w;
        uint2 h, l;
        split4v(f, &h, &l);
        fh4[base + (size_t)t * D4] = h;
        fl4[base + (size_t)t * D4] = l;
    }
}

// final router: sum 8 deterministic partials, add bias, softmax over 3
__global__ void router_final(const float* __restrict__ lampart,
                             const float* __restrict__ rb2,
                             float* __restrict__ lam) {
    int row = blockIdx.x * blockDim.x + threadIdx.x;
    if (row >= BB * TT) return;
    float z0 = rb2[0], z1 = rb2[1], z2 = rb2[2];
    #pragma unroll
    for (int p = 0; p < 8; ++p) {
        const float* q = lampart + ((size_t)row * 8 + p) * 3;
        z0 += q[0]; z1 += q[1]; z2 += q[2];
    }
    float m = fmaxf(z0, fmaxf(z1, z2));
    float e0 = expf(z0 - m), e1 = expf(z1 - m), e2 = expf(z2 - m);
    float inv = 1.0f / (e0 + e1 + e2);
    lam[(size_t)row * 3 + 0] = e0 * inv;
    lam[(size_t)row * 3 + 1] = e1 * inv;
    lam[(size_t)row * 3 + 2] = e2 * inv;
}

// ---------------- pipelined split-bf16 tensor-core GEMM ----------------
#define GEMM_SMEM (2 * 2 * BM * 40 * 2 * 2)

template<int MODE>
__global__ void __launch_bounds__(256, 2) mma_gemm(
    const __nv_bfloat16* __restrict__ Ahi, const __nv_bfloat16* __restrict__ Alo,
    const __nv_bfloat16* __restrict__ Bhi, const __nv_bfloat16* __restrict__ Blo,
    const __nv_bfloat16* __restrict__ B2hi, const __nv_bfloat16* __restrict__ B2lo,
    const float* __restrict__ bias,
    const float* __restrict__ rw2, float* __restrict__ lampart,
    float* __restrict__ Cf, float* __restrict__ Cf2,
    __nv_bfloat16* __restrict__ Chi, __nv_bfloat16* __restrict__ Clo,
    __nv_bfloat16* __restrict__ C2hi, __nv_bfloat16* __restrict__ C2lo,
    int M, int N, int K, int lda, int ldb)
{
    extern __shared__ __align__(16) char dynsmem[];
    __nv_bfloat16* sA = reinterpret_cast<__nv_bfloat16*>(dynsmem);
    __nv_bfloat16* sB = sA + 2 * 2 * BM * 40;

    int tid = threadIdx.x;
    int lane = tid & 31;
    int warp = tid >> 5;
    int wm = warp >> 2;
    int wn = warp & 3;
    int row0 = blockIdx.y * BM;

    int nb = N / BN;
    int which = 0;
    int bx = blockIdx.x;
    if (MODE == M_KV2) { which = bx / nb; bx -= which * nb; }
    int col0 = bx * BN;

    const __nv_bfloat16* Bh = (MODE == M_KV2 && which) ? B2hi : Bhi;
    const __nv_bfloat16* Bl = (MODE == M_KV2 && which) ? B2lo : Blo;

    float acc[4][4][4];
    #pragma unroll
    for (int a = 0; a < 4; ++a)
        #pragma unroll
        for (int b = 0; b < 4; ++b)
            #pragma unroll
            for (int c = 0; c < 4; ++c) acc[a][b][c] = 0.f;

    auto issue = [&](int k0, int st) {
        #pragma unroll
        for (int it = 0; it < 2; ++it) {
            int e = tid + it * 256;
            int r = e >> 2;
            int kc = (e & 3) * 8;
            size_t ao;
            if (MODE == M_OUT) {
                int gm = row0 + r, gk = k0 + kc;
                int b = gm >> 10, t = gm & (TT - 1);
                int h = gk >> 7, c = gk & (DHD - 1);
                ao = (((size_t)b * HH + h) * TT + t) * DHD + c;
            } else {
                ao = (size_t)(row0 + r) * lda + k0 + kc;
            }
            cp16(s2u(&sA[((st * 2 + 0) * BM + r) * 40 + kc]), Ahi + ao);
            cp16(s2u(&sA[((st * 2 + 1) * BM + r) * 40 + kc]), Alo + ao);
            size_t bo = (size_t)(col0 + r) * ldb + k0 + kc;
            cp16(s2u(&sB[((st * 2 + 0) * BM + r) * 40 + kc]), Bh + bo);
            cp16(s2u(&sB[((st * 2 + 1) * BM + r) * 40 + kc]), Bl + bo);
        }
    };

    int nIter = K / BKS;
    issue(0, 0);
    cp_commit();

    for (int i = 0; i < nIter; ++i) {
        int st = i & 1;
        if (i + 1 < nIter) {
            issue((i + 1) * BKS, (i + 1) & 1);
            cp_commit();
            cp_wait<1>();
        } else {
            cp_wait<0>();
        }
        __syncthreads();

        #pragma unroll
        for (int ks = 0; ks < BKS; ks += 16) {
            uint32_t afr[2][4][4];
            uint32_t bfr[2][4][2];
            #pragma unroll
            for (int mt = 0; mt < 4; ++mt) {
                int r = wm * 64 + mt * 16 + (lane & 15);
                int c = ks + (lane >> 4) * 8;
                ldsm4(afr[0][mt], s2u(&sA[((st * 2 + 0) * BM + r) * 40 + c]));
                ldsm4(afr[1][mt], s2u(&sA[((st * 2 + 1) * BM + r) * 40 + c]));
            }
            #pragma unroll
            for (int nt = 0; nt < 4; ++nt) {
                int r = wn * 32 + nt * 8 + (lane & 7);
                int c = ks + ((lane >> 3) & 1) * 8;
                ldsm2(bfr[0][nt], s2u(&sB[((st * 2 + 0) * BM + r) * 40 + c]));
                ldsm2(bfr[1][nt], s2u(&sB[((st * 2 + 1) * BM + r) * 40 + c]));
            }
            #pragma unroll
            for (int mt = 0; mt < 4; ++mt)
                #pragma unroll
                for (int nt = 0; nt < 4; ++nt) {
                    mma16816(acc[mt][nt], afr[0][mt], bfr[0][nt]);
                    mma16816(acc[mt][nt], afr[0][mt], bfr[1][nt]);
                    mma16816(acc[mt][nt], afr[1][mt], bfr[0][nt]);
                }
        }
        __syncthreads();
    }

    int g = lane >> 2, tg = lane & 3;

    if (MODE == M_HDN) {
        float zr[8][3];
        #pragma unroll
        for (int r = 0; r < 8; ++r)
            #pragma unroll
            for (int j = 0; j < 3; ++j) zr[r][j] = 0.f;

        #pragma unroll
        for (int mt = 0; mt < 4; ++mt)
            #pragma unroll
            for (int nt = 0; nt < 4; ++nt)
                #pragma unroll
                for (int i = 0; i < 4; ++i) {
                    int n = col0 + wn * 32 + nt * 8 + tg * 2 + (i & 1);
                    float v = acc[mt][nt][i] + bias[n];
                    v = v / (1.f + expf(-v));
                    int ri = mt * 2 + (i >> 1);
                    zr[ri][0] += v * rw2[n];
                    zr[ri][1] += v * rw2[DHALF + n];
                    zr[ri][2] += v * rw2[2 * DHALF + n];
                }
        #pragma unroll
        for (int r = 0; r < 8; ++r)
            #pragma unroll
            for (int j = 0; j < 3; ++j) {
                zr[r][j] += __shfl_xor_sync(0xffffffffu, zr[r][j], 1);
                zr[r][j] += __shfl_xor_sync(0xffffffffu, zr[r][j], 2);
            }
        __shared__ float zsm[4][128][3];
        if (tg == 0) {
            #pragma unroll
            for (int r = 0; r < 8; ++r) {
                int lr = wm * 64 + (r >> 1) * 16 + g + (r & 1) * 8;
                #pragma unroll
                for (int j = 0; j < 3; ++j) zsm[wn][lr][j] = zr[r][j];
            }
        }
        __syncthreads();
        if (tid < 128) {
            int gm = row0 + tid;
            float* dst = lampart + ((size_t)gm * 8 + blockIdx.x) * 3;
            #pragma unroll
            for (int j = 0; j < 3; ++j)
                dst[j] = zsm[0][tid][j] + zsm[1][tid][j] + zsm[2][tid][j] + zsm[3][tid][j];
        }
        return;
    }

    #pragma unroll
    for (int mt = 0; mt < 4; ++mt)
        #pragma unroll
        for (int nt = 0; nt < 4; ++nt)
            #pragma unroll
            for (int i = 0; i < 4; ++i) {
                int m = row0 + wm * 64 + mt * 16 + g + (i >> 1) * 8;
                int n = col0 + wn * 32 + nt * 8 + tg * 2 + (i & 1);
                float v = acc[mt][nt][i];
                if (MODE == M_Q) {
                    size_t idx = (size_t)m * N + n;
                    split2(v, &Chi[idx], &Clo[idx]);
                } else if (MODE == M_KV2) {
                    int b = m >> 10, t = m & (TT - 1);
                    int h = n >> 7, c = n & (DHD - 1);
                    size_t idx = (((size_t)b * HH + h) * TT + t) * DHD + c;
                    if (which == 0) {
                        Cf[idx] = v;
                        split2(v, &Chi[idx], &Clo[idx]);
                    } else {
                        Cf2[idx] = v;
                        split2(v, &C2hi[idx], &C2lo[idx]);
                    }
                } else {
                    Cf[(size_t)m * N + n] = v;
                }
            }
}

// ---------------- flash attention (R11 proven version) ----------------
// Q hi-only; PV drops pl term. One q-tile per CTA, reversed order.
#define FL_PITCH 136
#define FL_TILE  (128 * FL_PITCH)
#define FLASH_SMEM (5 * FL_TILE * 2)

__global__ void __launch_bounds__(256) flash_kernel(
    const __nv_bfloat16* __restrict__ qh_,
    const __nv_bfloat16* __restrict__ khh, const __nv_bfloat16* __restrict__ khl,
    const __nv_bfloat16* __restrict__ vhh, const __nv_bfloat16* __restrict__ vhl,
    __nv_bfloat16* __restrict__ aoh, __nv_bfloat16* __restrict__ aol,
    float scale)
{
    extern __shared__ __align__(16) char fsm[];
    __nv_bfloat16* sQh = reinterpret_cast<__nv_bfloat16*>(fsm);
    __nv_bfloat16* sKh = sQh + FL_TILE;
    __nv_bfloat16* sKl = sKh + FL_TILE;
    __nv_bfloat16* sVh = sKl + FL_TILE;
    __nv_bfloat16* sVl = sVh + FL_TILE;

    int tid = threadIdx.x;
    int lane = tid & 31;
    int wid = tid >> 5;
    int g = lane >> 2, tg = lane & 3;

    int qb = gridDim.x - 1 - blockIdx.x;   // heavy blocks first
    int z = blockIdx.y;
    int b = z / HH, h = z % HH;
    int row0 = qb * 128;

    const __nv_bfloat16* qbh = qh_ + (size_t)b * TT * DD + (size_t)h * DHD;
    const __nv_bfloat16* kbh = khh + (size_t)z * TT * DHD;
    const __nv_bfloat16* kbl = khl + (size_t)z * TT * DHD;
    const __nv_bfloat16* vbh = vhh + (size_t)z * TT * DHD;
    const __nv_bfloat16* vbl = vhl + (size_t)z * TT * DHD;

    auto loadK = [&](int kb2) {
        for (int e = tid; e < 128 * 16; e += 256) {
            int r = e >> 4, c8 = (e & 15) * 8;
            size_t go = (size_t)(kb2 * 128 + r) * DHD + c8;
            cp16(s2u(&sKh[r * FL_PITCH + c8]), kbh + go);
            cp16(s2u(&sKl[r * FL_PITCH + c8]), kbl + go);
        }
    };
    auto loadV = [&](int kb2) {
        for (int e = tid; e < 128 * 16; e += 256) {
            int r = e >> 4, c8 = (e & 15) * 8;
            size_t go = (size_t)(kb2 * 128 + r) * DHD + c8;
            cp16(s2u(&sVh[r * FL_PITCH + c8]), vbh + go);
            cp16(s2u(&sVl[r * FL_PITCH + c8]), vbl + go);
        }
    };

    for (int e = tid; e < 128 * 16; e += 256) {
        int r = e >> 4, c8 = (e & 15) * 8;
        *reinterpret_cast<uint4*>(&sQh[r * FL_PITCH + c8]) =
            *reinterpret_cast<const uint4*>(qbh + (size_t)(row0 + r) * DD + c8);
    }
    loadK(0); cp_commit();
    loadV(0); cp_commit();

    float accO[16][4];
    #pragma unroll
    for (int i = 0; i < 16; ++i)
        #pragma unroll
        for (int j = 0; j < 4; ++j) accO[i][j] = 0.f;
    float mrun0 = -INFINITY, mrun1 = -INFINITY;
    float lrun0 = 0.f, lrun1 = 0.f;

    for (int kb = 0; kb <= qb; ++kb) {
        cp_wait<1>();
        __syncthreads();

        // ---- S = Qh (Kh + Kl)^T ----
        float S[16][4];
        #pragma unroll
        for (int i = 0; i < 16; ++i)
            #pragma unroll
            for (int j = 0; j < 4; ++j) S[i][j] = 0.f;

        #pragma unroll
        for (int ks = 0; ks < 8; ++ks) {
            uint32_t qf[4];
            {
                int r = wid * 16 + (lane & 15);
                int c = ks * 16 + (lane >> 4) * 8;
                ldsm4(qf, s2u(&sQh[r * FL_PITCH + c]));
            }
            #pragma unroll
            for (int nt = 0; nt < 16; ++nt) {
                uint32_t bh[2], bl[2];
                int r = nt * 8 + (lane & 7);
                int c = ks * 16 + ((lane >> 3) & 1) * 8;
                ldsm2(bh, s2u(&sKh[r * FL_PITCH + c]));
                ldsm2(bl, s2u(&sKl[r * FL_PITCH + c]));
                mma16816(S[nt], qf, bh);
                mma16816(S[nt], qf, bl);
            }
        }
        __syncthreads();
        if (kb < qb) { loadK(kb + 1); cp_commit(); }

        // ---- scale + mask + online softmax ----
        bool diag = (kb == qb);
        #pragma unroll
        for (int nt = 0; nt < 16; ++nt)
            #pragma unroll
            for (int j = 0; j < 4; ++j) {
                float v = S[nt][j] * scale;
                if (diag) {
                    int n = nt * 8 + tg * 2 + (j & 1);
                    int m = wid * 16 + g + ((j >> 1) ? 8 : 0);
                    if (n > m) v = -INFINITY;
                }
                S[nt][j] = v;
            }

        float mx0 = -INFINITY, mx1 = -INFINITY;
        #pragma unroll
        for (int nt = 0; nt < 16; ++nt) {
            mx0 = fmaxf(mx0, fmaxf(S[nt][0], S[nt][1]));
            mx1 = fmaxf(mx1, fmaxf(S[nt][2], S[nt][3]));
        }
        mx0 = fmaxf(mx0, __shfl_xor_sync(0xffffffffu, mx0, 1));
        mx0 = fmaxf(mx0, __shfl_xor_sync(0xffffffffu, mx0, 2));
        mx1 = fmaxf(mx1, __shfl_xor_sync(0xffffffffu, mx1, 1));
        mx1 = fmaxf(mx1, __shfl_xor_sync(0xffffffffu, mx1, 2));

        float mn0 = fmaxf(mrun0, mx0);
        float mn1 = fmaxf(mrun1, mx1);
        float al0 = expf(mrun0 - mn0);
        float al1 = expf(mrun1 - mn1);
        mrun0 = mn0; mrun1 = mn1;

        float ls0 = 0.f, ls1 = 0.f;
        #pragma unroll
        for (int nt = 0; nt < 16; ++nt) {
            float e0 = expf(S[nt][0] - mn0);
            float e1 = expf(S[nt][1] - mn0);
            float e2 = expf(S[nt][2] - mn1);
            float e3 = expf(S[nt][3] - mn1);
            S[nt][0] = e0; S[nt][1] = e1; S[nt][2] = e2; S[nt][3] = e3;
            ls0 += e0 + e1;
            ls1 += e2 + e3;
        }
        lrun0 = lrun0 * al0 + ls0;
        lrun1 = lrun1 * al1 + ls1;

        #pragma unroll
        for (int nt = 0; nt < 16; ++nt) {
            accO[nt][0] *= al0; accO[nt][1] *= al0;
            accO[nt][2] *= al1; accO[nt][3] *= al1;
        }

        if (kb < qb) cp_wait<1>(); else cp_wait<0>();
        __syncthreads();

        // ---- O += Ph (Vh + Vl) ----
        #pragma unroll
        for (int kk = 0; kk < 8; ++kk) {
            uint32_t ph[4];
            ph[0] = packb2(S[2 * kk][0],     S[2 * kk][1]);
            ph[1] = packb2(S[2 * kk][2],     S[2 * kk][3]);
            ph[2] = packb2(S[2 * kk + 1][0], S[2 * kk + 1][1]);
            ph[3] = packb2(S[2 * kk + 1][2], S[2 * kk + 1][3]);
            #pragma unroll
            for (int ndt = 0; ndt < 16; ++ndt) {
                uint32_t vh2[2], vl2[2];
                int rr = kk * 16 + (lane & 15);
                int cc = ndt * 8;
                ldsm2t(vh2, s2u(&sVh[rr * FL_PITCH + cc]));
                ldsm2t(vl2, s2u(&sVl[rr * FL_PITCH + cc]));
                mma16816(accO[ndt], ph, vh2);
                mma16816(accO[ndt], ph, vl2);
            }
        }
        __syncthreads();
        if (kb < qb) { loadV(kb + 1); cp_commit(); }
    }

    lrun0 += __shfl_xor_sync(0xffffffffu, lrun0, 1);
    lrun0 += __shfl_xor_sync(0xffffffffu, lrun0, 2);
    lrun1 += __shfl_xor_sync(0xffffffffu, lrun1, 1);
    lrun1 += __shfl_xor_sync(0xffffffffu, lrun1, 2);
    float inv0 = 1.0f / lrun0;
    float inv1 = 1.0f / lrun1;

    size_t obase = (size_t)z * TT * DHD;
    #pragma unroll
    for (int ndt = 0; ndt < 16; ++ndt)
        #pragma unroll
        for (int j = 0; j < 4; ++j) {
            int m = row0 + wid * 16 + g + ((j >> 1) ? 8 : 0);
            int n = ndt * 8 + tg * 2 + (j & 1);
            float v = accO[ndt][j] * ((j >> 1) ? inv1 : inv0);
            size_t idx = obase + (size_t)m * DHD + n;
            split2(v, &aoh[idx], &aol[idx]);
        }
}

// ---------------- host ----------------
#define SYMADDR(var, sym) cudaGetSymbolAddress((void**)&var, sym)

extern "C" void kernel_launch(void* const* d_in, const int* in_sizes, int n_in,
                              void* d_out, int out_size) {
    const float* x   = (const float*)d_in[0];
    const float* l3  = (const float*)d_in[1];
    const float* wq  = (const float*)d_in[2];
    const float* wk  = (const float*)d_in[3];
    const float* wv  = (const float*)d_in[4];
    const float* wo  = (const float*)d_in[5];
    const float* rw1 = (const float*)d_in[6];
    const float* rb1 = (const float*)d_in[7];
    const float* rw2 = (const float*)d_in[8];
    const float* rb2 = (const float*)d_in[9];

    float* out     = (float*)d_out;
    float* kh_out  = out    + (size_t)BB * TT * DD;
    float* vh_out  = kh_out + (size_t)BB * TT * DD;
    float* lam_out = vh_out + (size_t)BB * TT * DD;

    float *carryA, *carryB, *lampart;
    SYMADDR(carryA, g_carryA); SYMADDR(carryB, g_carryB);
    SYMADDR(lampart, g_lampart);

    __nv_bfloat16 *xs_h,*xs_l, *wqs_h,*wqs_l, *wks_h,*wks_l, *wvs_h,*wvs_l,
                  *wos_h,*wos_l, *rw1s_h,*rw1s_l, *qs_h,*qs_l, *fs_h,*fs_l,
                  *khs_h,*khs_l, *vhs_h,*vhs_l, *aos_h,*aos_l;
    SYMADDR(xs_h, g_xs_h);     SYMADDR(xs_l, g_xs_l);
    SYMADDR(wqs_h, g_wqs_h);   SYMADDR(wqs_l, g_wqs_l);
    SYMADDR(wks_h, g_wks_h);   SYMADDR(wks_l, g_wks_l);
    SYMADDR(wvs_h, g_wvs_h);   SYMADDR(wvs_l, g_wvs_l);
    SYMADDR(wos_h, g_wos_h);   SYMADDR(wos_l, g_wos_l);
    SYMADDR(rw1s_h, g_rw1s_h); SYMADDR(rw1s_l, g_rw1s_l);
    SYMADDR(qs_h, g_qs_h);     SYMADDR(qs_l, g_qs_l);
    SYMADDR(fs_h, g_fs_h);     SYMADDR(fs_l, g_fs_l);
    SYMADDR(khs_h, g_khs_h);   SYMADDR(khs_l, g_khs_l);
    SYMADDR(vhs_h, g_vhs_h);   SYMADDR(vhs_l, g_vhs_l);
    SYMADDR(aos_h, g_aos_h);   SYMADDR(aos_l, g_aos_l);

    const int M = BB * TT;
    const float scale = 1.0f / sqrtf((float)DHD);
    const int NW4 = (int)((size_t)DD * DD / 4);

    cudaFuncSetAttribute(mma_gemm<M_Q>,   cudaFuncAttributeMaxDynamicSharedMemorySize, GEMM_SMEM);
    cudaFuncSetAttribute(mma_gemm<M_HDN>, cudaFuncAttributeMaxDynamicSharedMemorySize, GEMM_SMEM);
    cudaFuncSetAttribute(mma_gemm<M_KV2>, cudaFuncAttributeMaxDynamicSharedMemorySize, GEMM_SMEM);
    cudaFuncSetAttribute(mma_gemm<M_OUT>, cudaFuncAttributeMaxDynamicSharedMemorySize, GEMM_SMEM);
    cudaFuncSetAttribute(flash_kernel,    cudaFuncAttributeMaxDynamicSharedMemorySize, FLASH_SMEM);

    // weight splits (vectorized x4)
    split4_v4_kernel<<<(NW4 + 255) / 256, 256>>>(
        (const float4*)wq, (const float4*)wk, (const float4*)wv, (const float4*)wo,
        (uint2*)wqs_h, (uint2*)wqs_l, (uint2*)wks_h, (uint2*)wks_l,
        (uint2*)wvs_h, (uint2*)wvs_l, (uint2*)wos_h, (uint2*)wos_l, NW4);
    split_v4_kernel<<<(NW4 / 2 + 255) / 256, 256>>>(
        (const float4*)rw1, (uint2*)rw1s_h, (uint2*)rw1s_l, NW4 / 2);

    // EMA chunk scan fused with x split; then carries
    ema_chunk_split_v4<<<(BB * NC * D4 + 255) / 256, 256>>>(
        (const float4*)x, (float4*)carryA, (uint2*)xs_h, (uint2*)xs_l);
    ema_carry_v4<<<(BB * D4 + 255) / 256, 256>>>((const float4*)carryA, (float4*)carryB);

    // q = x @ wq^T
    mma_gemm<M_Q><<<dim3(DD / BN, M / BM), 256, GEMM_SMEM>>>(
        xs_h, xs_l, wqs_h, wqs_l, nullptr, nullptr, nullptr, nullptr, nullptr,
        nullptr, nullptr, qs_h, qs_l, nullptr, nullptr, M, DD, DD, DD, DD);

    // hdn + router partials fused
    mma_gemm<M_HDN><<<dim3(DHALF / BN, M / BM), 256, GEMM_SMEM>>>(
        qs_h, qs_l, rw1s_h, rw1s_l, nullptr, nullptr, rb1, rw2, lampart,
        nullptr, nullptr, nullptr, nullptr, nullptr, nullptr, M, DHALF, DD, DD, DD);

    // lam = softmax(sum partials + rb2)
    router_final<<<(M + 255) / 256, 256>>>(lampart, rb2, lam_out);

    // EMA rescan + fuse + split (single pass)
    ema_fuse_v4<<<(BB * NC * D4 + 255) / 256, 256>>>(
        (const float4*)x, (const float4*)carryB, (const float4*)l3, lam_out,
        (uint2*)fs_h, (uint2*)fs_l);

    // kh + vh in ONE launch
    mma_gemm<M_KV2><<<dim3(2 * DD / BN, M / BM), 256, GEMM_SMEM>>>(
        fs_h, fs_l, wks_h, wks_l, wvs_h, wvs_l, nullptr, nullptr, nullptr,
        kh_out, vh_out, khs_h, khs_l, vhs_h, vhs_l, M, DD, DD, DD, DD);

    // flash attention (R11 proven version)
    flash_kernel<<<dim3(TT / 128, BB * HH), 256, FLASH_SMEM>>>(
        qs_h, khs_h, khs_l, vhs_h, vhs_l, aos_h, aos_l, scale);

    // out = concat_heads(ao) @ wo^T
    mma_gemm<M_OUT><<<dim3(DD / BN, M / BM), 256, GEMM_SMEM>>>(
        aos_h, aos_l, wos_h, wos_l, nullptr, nullptr, nullptr, nullptr, nullptr,
        out, nullptr, nullptr, nullptr, nullptr, nullptr, M, DD, DD, DD, DD);
}

// round 15
// speedup vs baseline: 1.5408x; 1.0452x over previous
#include <cuda_runtime.h>
#include <cuda_bf16.h>
#include <math.h>
#include <stdint.h>

#define BB 2
#define TT 1024
#define DD 2048
#define HH 16
#define DHD 128
#define DHALF 1024

#define BM 128
#define BN 128
#define BKS 32

// EMA chunking: 64 chunks of 16 steps
#define NC 64
#define CL 16
#define BETA 0.9f
#define OMB  0.1f
#define BETA_L 0.1853020188851841f   // 0.9^16

// GEMM modes
#define M_Q 0
#define M_HDN 1
#define M_KV2 2
#define M_OUT 3

// ---------------- device scratch ----------------
__device__ float g_carryA[(size_t)BB*NC*DD];
__device__ float g_carryB[(size_t)BB*NC*DD];
__device__ float g_lampart[(size_t)BB*TT*8*3];   // per-block router partials

#define DECL_SPLIT(name, count) \
    __device__ __nv_bfloat16 name##_h[count]; \
    __device__ __nv_bfloat16 name##_l[count];

DECL_SPLIT(g_xs,   (size_t)BB*TT*DD)
DECL_SPLIT(g_wqs,  (size_t)DD*DD)
DECL_SPLIT(g_wks,  (size_t)DD*DD)
DECL_SPLIT(g_wvs,  (size_t)DD*DD)
DECL_SPLIT(g_wos,  (size_t)DD*DD)
DECL_SPLIT(g_rw1s, (size_t)DHALF*DD)
__device__ __nv_bfloat16 g_qs_h[(size_t)BB*TT*DD];   // qs: hi only (lo is dead)
DECL_SPLIT(g_fs,   (size_t)BB*TT*DD)
DECL_SPLIT(g_khs,  (size_t)BB*TT*DD)
DECL_SPLIT(g_vhs,  (size_t)BB*TT*DD)
DECL_SPLIT(g_aos,  (size_t)BB*TT*DD)

// ---------------- helpers ----------------
__device__ __forceinline__ void split2(float v, __nv_bfloat16* hi, __nv_bfloat16* lo) {
    __nv_bfloat16 h = __float2bfloat16(v);
    *hi = h;
    *lo = __float2bfloat16(v - __bfloat162float(h));
}
__device__ __forceinline__ uint32_t s2u(const void* p) {
    return (uint32_t)__cvta_generic_to_shared(p);
}
__device__ __forceinline__ void ldsm4(uint32_t* r, uint32_t addr) {
    asm volatile("ldmatrix.sync.aligned.m8n8.x4.shared.b16 {%0,%1,%2,%3}, [%4];"
                 : "=r"(r[0]), "=r"(r[1]), "=r"(r[2]), "=r"(r[3]) : "r"(addr));
}
__device__ __forceinline__ void ldsm2(uint32_t* r, uint32_t addr) {
    asm volatile("ldmatrix.sync.aligned.m8n8.x2.shared.b16 {%0,%1}, [%2];"
                 : "=r"(r[0]), "=r"(r[1]) : "r"(addr));
}
__device__ __forceinline__ void ldsm2t(uint32_t* r, uint32_t addr) {
    asm volatile("ldmatrix.sync.aligned.m8n8.x2.trans.shared.b16 {%0,%1}, [%2];"
                 : "=r"(r[0]), "=r"(r[1]) : "r"(addr));
}
__device__ __forceinline__ void mma16816(float* c, const uint32_t* a, const uint32_t* b) {
    asm volatile("mma.sync.aligned.m16n8k16.row.col.f32.bf16.bf16.f32 "
                 "{%0,%1,%2,%3}, {%4,%5,%6,%7}, {%8,%9}, {%0,%1,%2,%3};"
                 : "+f"(c[0]), "+f"(c[1]), "+f"(c[2]), "+f"(c[3])
                 : "r"(a[0]), "r"(a[1]), "r"(a[2]), "r"(a[3]), "r"(b[0]), "r"(b[1]));
}
__device__ __forceinline__ void cp16(uint32_t saddr, const void* g) {
    asm volatile("cp.async.cg.shared.global [%0], [%1], 16;" :: "r"(saddr), "l"(g));
}
__device__ __forceinline__ void cp_commit() {
    asm volatile("cp.async.commit_group;");
}
template<int N> __device__ __forceinline__ void cp_wait() {
    asm volatile("cp.async.wait_group %0;" :: "n"(N));
}
__device__ __forceinline__ uint32_t packb2(float lo_k, float hi_k) {
    __nv_bfloat162 t = __floats2bfloat162_rn(lo_k, hi_k);   // .x = low half
    return *reinterpret_cast<uint32_t*>(&t);
}

// split float4 -> hi uint2 (4 bf16) + lo uint2
__device__ __forceinline__ void split4v(float4 v, uint2* hi, uint2* lo) {
    __nv_bfloat16 h0 = __float2bfloat16(v.x);
    __nv_bfloat16 h1 = __float2bfloat16(v.y);
    __nv_bfloat16 h2 = __float2bfloat16(v.z);
    __nv_bfloat16 h3 = __float2bfloat16(v.w);
    float r0 = v.x - __bfloat162float(h0);
    float r1 = v.y - __bfloat162float(h1);
    float r2 = v.z - __bfloat162float(h2);
    float r3 = v.w - __bfloat162float(h3);
    __nv_bfloat162 p01; p01.x = h0; p01.y = h1;
    __nv_bfloat162 p23; p23.x = h2; p23.y = h3;
    hi->x = *reinterpret_cast<uint32_t*>(&p01);
    hi->y = *reinterpret_cast<uint32_t*>(&p23);
    lo->x = packb2(r0, r1);
    lo->y = packb2(r2, r3);
}

// ---------------- elementwise kernels (vectorized x4) ----------------
__global__ void split_v4_kernel(const float4* __restrict__ s,
                                uint2* __restrict__ hi, uint2* __restrict__ lo, int n4) {
    int i = blockIdx.x * blockDim.x + threadIdx.x;
    if (i >= n4) return;
    uint2 h, l;
    split4v(s[i], &h, &l);
    hi[i] = h; lo[i] = l;
}

__global__ void split4_v4_kernel(const float4* __restrict__ a, const float4* __restrict__ b,
                                 const float4* __restrict__ c, const float4* __restrict__ d,
                                 uint2* __restrict__ ah, uint2* __restrict__ al,
                                 uint2* __restrict__ bh, uint2* __restrict__ bl,
                                 uint2* __restrict__ ch, uint2* __restrict__ cl,
                                 uint2* __restrict__ dh, uint2* __restrict__ dl, int n4) {
    int i = blockIdx.x * blockDim.x + threadIdx.x;
    if (i >= n4) return;
    uint2 h, l;
    split4v(a[i], &h, &l); ah[i] = h; al[i] = l;
    split4v(b[i], &h, &l); bh[i] = h; bl[i] = l;
    split4v(c[i], &h, &l); ch[i] = h; cl[i] = l;
    split4v(d[i], &h, &l); dh[i] = h; dl[i] = l;
}

// ---- chunk-parallel EMA (NC=64 chunks of CL=16), float4-vectorized ----
// Fused: also emits the bf16 hi/lo split of x.
#define D4 (DD / 4)

__global__ void ema_chunk_split_v4(const float4* __restrict__ x4,
                                   float4* __restrict__ carryA4,
                                   uint2* __restrict__ xh4, uint2* __restrict__ xl4) {
    int idx = blockIdx.x * blockDim.x + threadIdx.x;
    if (idx >= BB * NC * D4) return;
    int c4 = idx % D4;
    int bc = idx / D4;
    int chunk = bc % NC;
    int b = bc / NC;
    size_t base = ((size_t)b * TT + (size_t)chunk * CL) * D4 + c4;
    float4 s = make_float4(0.f, 0.f, 0.f, 0.f);
    #pragma unroll
    for (int t = 0; t < CL; ++t) {
        float4 v = x4[base + (size_t)t * D4];
        s.x = BETA * s.x + OMB * v.x;
        s.y = BETA * s.y + OMB * v.y;
        s.z = BETA * s.z + OMB * v.z;
        s.w = BETA * s.w + OMB * v.w;
        uint2 h, l;
        split4v(v, &h, &l);
        xh4[base + (size_t)t * D4] = h;
        xl4[base + (size_t)t * D4] = l;
    }
    carryA4[idx] = s;
}

// scalar carry propagation: BB*DD threads (coalesced, 16 blocks)
__global__ void ema_carry_s(const float* __restrict__ carryA, float* __restrict__ carryB) {
    int idx = blockIdx.x * blockDim.x + threadIdx.x;
    if (idx >= BB * DD) return;
    int c = idx % DD;
    int b = idx / DD;
    float cin = 0.f;
    #pragma unroll
    for (int j = 0; j < NC; ++j) {
        size_t off = ((size_t)b * NC + j) * DD + c;
        carryB[off] = cin;
        cin = BETA_L * cin + carryA[off];
    }
}

// rescan + fuse + split, all in one pass
__global__ void ema_fuse_v4(const float4* __restrict__ x4, const float4* __restrict__ carryB4,
                            const float4* __restrict__ l34, const float* __restrict__ lam,
                            uint2* __restrict__ fh4, uint2* __restrict__ fl4) {
    int idx = blockIdx.x * blockDim.x + threadIdx.x;
    if (idx >= BB * NC * D4) return;
    int c4 = idx % D4;
    int bc = idx / D4;
    int chunk = bc % NC;
    int b = bc / NC;
    size_t base = ((size_t)b * TT + (size_t)chunk * CL) * D4 + c4;
    float4 s = carryB4[idx];
    float4 m = l34[(size_t)b * D4 + c4];
    int row0 = b * TT + chunk * CL;
    #pragma unroll
    for (int t = 0; t < CL; ++t) {
        float4 v = x4[base + (size_t)t * D4];
        s.x = BETA * s.x + OMB * v.x;
        s.y = BETA * s.y + OMB * v.y;
        s.z = BETA * s.z + OMB * v.z;
        s.w = BETA * s.w + OMB * v.w;
        int row = row0 + t;
        float a0 = lam[(size_t)row * 3 + 0];
        float a1 = lam[(size_t)row * 3 + 1];
        float a2 = lam[(size_t)row * 3 + 2];
        float4 f;
        f.x = a0 * v.x + a1 * s.x + a2 * m.x;
        f.y = a0 * v.y + a1 * s.y + a2 * m.y;
        f.z = a0 * v.z + a1 * s.z + a2 * m.z;
        f.w = a0 * v.w + a1 * s.w + a2 * m.w;
        uint2 h, l;
        split4v(f, &h, &l);
        fh4[base + (size_t)t * D4] = h;
        fl4[base + (size_t)t * D4] = l;
    }
}

// final router: sum 8 deterministic partials, add bias, softmax over 3
__global__ void router_final(const float* __restrict__ lampart,
                             const float* __restrict__ rb2,
                             float* __restrict__ lam) {
    int row = blockIdx.x * blockDim.x + threadIdx.x;
    if (row >= BB * TT) return;
    float z0 = rb2[0], z1 = rb2[1], z2 = rb2[2];
    #pragma unroll
    for (int p = 0; p < 8; ++p) {
        const float* q = lampart + ((size_t)row * 8 + p) * 3;
        z0 += q[0]; z1 += q[1]; z2 += q[2];
    }
    float m = fmaxf(z0, fmaxf(z1, z2));
    float e0 = expf(z0 - m), e1 = expf(z1 - m), e2 = expf(z2 - m);
    float inv = 1.0f / (e0 + e1 + e2);
    lam[(size_t)row * 3 + 0] = e0 * inv;
    lam[(size_t)row * 3 + 1] = e1 * inv;
    lam[(size_t)row * 3 + 2] = e2 * inv;
}

// ---------------- pipelined split-bf16 tensor-core GEMM ----------------
// M_HDN: 2-term (A hi only: errors average out through the router dot+softmax).
#define GEMM_SMEM (2 * 2 * BM * 40 * 2 * 2)

template<int MODE>
__global__ void __launch_bounds__(256, 2) mma_gemm(
    const __nv_bfloat16* __restrict__ Ahi, const __nv_bfloat16* __restrict__ Alo,
    const __nv_bfloat16* __restrict__ Bhi, const __nv_bfloat16* __restrict__ Blo,
    const __nv_bfloat16* __restrict__ B2hi, const __nv_bfloat16* __restrict__ B2lo,
    const float* __restrict__ bias,
    const float* __restrict__ rw2, float* __restrict__ lampart,
    float* __restrict__ Cf, float* __restrict__ Cf2,
    __nv_bfloat16* __restrict__ Chi, __nv_bfloat16* __restrict__ Clo,
    __nv_bfloat16* __restrict__ C2hi, __nv_bfloat16* __restrict__ C2lo,
    int M, int N, int K, int lda, int ldb)
{
    extern __shared__ __align__(16) char dynsmem[];
    __nv_bfloat16* sA = reinterpret_cast<__nv_bfloat16*>(dynsmem);
    __nv_bfloat16* sB = sA + 2 * 2 * BM * 40;

    int tid = threadIdx.x;
    int lane = tid & 31;
    int warp = tid >> 5;
    int wm = warp >> 2;
    int wn = warp & 3;
    int row0 = blockIdx.y * BM;

    int nb = N / BN;
    int which = 0;
    int bx = blockIdx.x;
    if (MODE == M_KV2) { which = bx / nb; bx -= which * nb; }
    int col0 = bx * BN;

    const __nv_bfloat16* Bh = (MODE == M_KV2 && which) ? B2hi : Bhi;
    const __nv_bfloat16* Bl = (MODE == M_KV2 && which) ? B2lo : Blo;

    float acc[4][4][4];
    #pragma unroll
    for (int a = 0; a < 4; ++a)
        #pragma unroll
        for (int b = 0; b < 4; ++b)
            #pragma unroll
            for (int c = 0; c < 4; ++c) acc[a][b][c] = 0.f;

    auto issue = [&](int k0, int st) {
        #pragma unroll
        for (int it = 0; it < 2; ++it) {
            int e = tid + it * 256;
            int r = e >> 2;
            int kc = (e & 3) * 8;
            size_t ao;
            if (MODE == M_OUT) {
                int gm = row0 + r, gk = k0 + kc;
                int b = gm >> 10, t = gm & (TT - 1);
                int h = gk >> 7, c = gk & (DHD - 1);
                ao = (((size_t)b * HH + h) * TT + t) * DHD + c;
            } else {
                ao = (size_t)(row0 + r) * lda + k0 + kc;
            }
            cp16(s2u(&sA[((st * 2 + 0) * BM + r) * 40 + kc]), Ahi + ao);
            if (MODE != M_HDN)
                cp16(s2u(&sA[((st * 2 + 1) * BM + r) * 40 + kc]), Alo + ao);
            size_t bo = (size_t)(col0 + r) * ldb + k0 + kc;
            cp16(s2u(&sB[((st * 2 + 0) * BM + r) * 40 + kc]), Bh + bo);
            cp16(s2u(&sB[((st * 2 + 1) * BM + r) * 40 + kc]), Bl + bo);
        }
    };

    int nIter = K / BKS;
    issue(0, 0);
    cp_commit();

    for (int i = 0; i < nIter; ++i) {
        int st = i & 1;
        if (i + 1 < nIter) {
            issue((i + 1) * BKS, (i + 1) & 1);
            cp_commit();
            cp_wait<1>();
        } else {
            cp_wait<0>();
        }
        __syncthreads();

        #pragma unroll
        for (int ks = 0; ks < BKS; ks += 16) {
            uint32_t afr[2][4][4];
            uint32_t bfr[2][4][2];
            #pragma unroll
            for (int mt = 0; mt < 4; ++mt) {
                int r = wm * 64 + mt * 16 + (lane & 15);
                int c = ks + (lane >> 4) * 8;
                ldsm4(afr[0][mt], s2u(&sA[((st * 2 + 0) * BM + r) * 40 + c]));
                if (MODE != M_HDN)
                    ldsm4(afr[1][mt], s2u(&sA[((st * 2 + 1) * BM + r) * 40 + c]));
            }
            #pragma unroll
            for (int nt = 0; nt < 4; ++nt) {
                int r = wn * 32 + nt * 8 + (lane & 7);
                int c = ks + ((lane >> 3) & 1) * 8;
                ldsm2(bfr[0][nt], s2u(&sB[((st * 2 + 0) * BM + r) * 40 + c]));
                ldsm2(bfr[1][nt], s2u(&sB[((st * 2 + 1) * BM + r) * 40 + c]));
            }
            #pragma unroll
            for (int mt = 0; mt < 4; ++mt)
                #pragma unroll
                for (int nt = 0; nt < 4; ++nt) {
                    mma16816(acc[mt][nt], afr[0][mt], bfr[0][nt]);
                    mma16816(acc[mt][nt], afr[0][mt], bfr[1][nt]);
                    if (MODE != M_HDN)
                        mma16816(acc[mt][nt], afr[1][mt], bfr[0][nt]);
                }
        }
        __syncthreads();
    }

    int g = lane >> 2, tg = lane & 3;

    if (MODE == M_HDN) {
        float zr[8][3];
        #pragma unroll
        for (int r = 0; r < 8; ++r)
            #pragma unroll
            for (int j = 0; j < 3; ++j) zr[r][j] = 0.f;

        #pragma unroll
        for (int mt = 0; mt < 4; ++mt)
            #pragma unroll
            for (int nt = 0; nt < 4; ++nt)
                #pragma unroll
                for (int i = 0; i < 4; ++i) {
                    int n = col0 + wn * 32 + nt * 8 + tg * 2 + (i & 1);
                    float v = acc[mt][nt][i] + bias[n];
                    v = v / (1.f + expf(-v));
                    int ri = mt * 2 + (i >> 1);
                    zr[ri][0] += v * rw2[n];
                    zr[ri][1] += v * rw2[DHALF + n];
                    zr[ri][2] += v * rw2[2 * DHALF + n];
                }
        #pragma unroll
        for (int r = 0; r < 8; ++r)
            #pragma unroll
            for (int j = 0; j < 3; ++j) {
                zr[r][j] += __shfl_xor_sync(0xffffffffu, zr[r][j], 1);
                zr[r][j] += __shfl_xor_sync(0xffffffffu, zr[r][j], 2);
            }
        __shared__ float zsm[4][128][3];
        if (tg == 0) {
            #pragma unroll
            for (int r = 0; r < 8; ++r) {
                int lr = wm * 64 + (r >> 1) * 16 + g + (r & 1) * 8;
                #pragma unroll
                for (int j = 0; j < 3; ++j) zsm[wn][lr][j] = zr[r][j];
            }
        }
        __syncthreads();
        if (tid < 128) {
            int gm = row0 + tid;
            float* dst = lampart + ((size_t)gm * 8 + blockIdx.x) * 3;
            #pragma unroll
            for (int j = 0; j < 3; ++j)
                dst[j] = zsm[0][tid][j] + zsm[1][tid][j] + zsm[2][tid][j] + zsm[3][tid][j];
        }
        return;
    }

    #pragma unroll
    for (int mt = 0; mt < 4; ++mt)
        #pragma unroll
        for (int nt = 0; nt < 4; ++nt)
            #pragma unroll
            for (int i = 0; i < 4; ++i) {
                int m = row0 + wm * 64 + mt * 16 + g + (i >> 1) * 8;
                int n = col0 + wn * 32 + nt * 8 + tg * 2 + (i & 1);
                float v = acc[mt][nt][i];
                if (MODE == M_Q) {
                    // hi-only output (lo is dead: flash + 2-term HDN both use hi)
                    Chi[(size_t)m * N + n] = __float2bfloat16(v);
                } else if (MODE == M_KV2) {
                    int b = m >> 10, t = m & (TT - 1);
                    int h = n >> 7, c = n & (DHD - 1);
                    size_t idx = (((size_t)b * HH + h) * TT + t) * DHD + c;
                    if (which == 0) {
                        Cf[idx] = v;
                        split2(v, &Chi[idx], &Clo[idx]);
                    } else {
                        Cf2[idx] = v;
                        split2(v, &C2hi[idx], &C2lo[idx]);
                    }
                } else {
                    Cf[(size_t)m * N + n] = v;
                }
            }
}

// ---------------- flash attention (unchanged from R13) ----------------
#define FL_PITCH 136
#define FL_TILE  (128 * FL_PITCH)
#define FLASH_SMEM (5 * FL_TILE * 2)

__global__ void __launch_bounds__(256) flash_kernel(
    const __nv_bfloat16* __restrict__ qh_,
    const __nv_bfloat16* __restrict__ khh, const __nv_bfloat16* __restrict__ khl,
    const __nv_bfloat16* __restrict__ vhh, const __nv_bfloat16* __restrict__ vhl,
    __nv_bfloat16* __restrict__ aoh, __nv_bfloat16* __restrict__ aol,
    float scale)
{
    extern __shared__ __align__(16) char fsm[];
    __nv_bfloat16* sQh = reinterpret_cast<__nv_bfloat16*>(fsm);
    __nv_bfloat16* sKh = sQh + FL_TILE;
    __nv_bfloat16* sKl = sKh + FL_TILE;
    __nv_bfloat16* sVh = sKl + FL_TILE;
    __nv_bfloat16* sVl = sVh + FL_TILE;

    int tid = threadIdx.x;
    int lane = tid & 31;
    int wid = tid >> 5;
    int g = lane >> 2, tg = lane & 3;

    int qb = gridDim.x - 1 - blockIdx.x;
    int z = blockIdx.y;
    int b = z / HH, h = z % HH;
    int row0 = qb * 128;

    const __nv_bfloat16* qbh = qh_ + (size_t)b * TT * DD + (size_t)h * DHD;
    const __nv_bfloat16* kbh = khh + (size_t)z * TT * DHD;
    const __nv_bfloat16* kbl = khl + (size_t)z * TT * DHD;
    const __nv_bfloat16* vbh = vhh + (size_t)z * TT * DHD;
    const __nv_bfloat16* vbl = vhl + (size_t)z * TT * DHD;

    auto loadK = [&](int kb2) {
        for (int e = tid; e < 128 * 16; e += 256) {
            int r = e >> 4, c8 = (e & 15) * 8;
            size_t go = (size_t)(kb2 * 128 + r) * DHD + c8;
            cp16(s2u(&sKh[r * FL_PITCH + c8]), kbh + go);
            cp16(s2u(&sKl[r * FL_PITCH + c8]), kbl + go);
        }
    };
    auto loadV = [&](int kb2) {
        for (int e = tid; e < 128 * 16; e += 256) {
            int r = e >> 4, c8 = (e & 15) * 8;
            size_t go = (size_t)(kb2 * 128 + r) * DHD + c8;
            cp16(s2u(&sVh[r * FL_PITCH + c8]), vbh + go);
            cp16(s2u(&sVl[r * FL_PITCH + c8]), vbl + go);
        }
    };

    for (int e = tid; e < 128 * 16; e += 256) {
        int r = e >> 4, c8 = (e & 15) * 8;
        *reinterpret_cast<uint4*>(&sQh[r * FL_PITCH + c8]) =
            *reinterpret_cast<const uint4*>(qbh + (size_t)(row0 + r) * DD + c8);
    }
    loadK(0); cp_commit();
    loadV(0); cp_commit();

    float accO[16][4];
    #pragma unroll
    for (int i = 0; i < 16; ++i)
        #pragma unroll
        for (int j = 0; j < 4; ++j) accO[i][j] = 0.f;
    float mrun0 = -INFINITY, mrun1 = -INFINITY;
    float lrun0 = 0.f, lrun1 = 0.f;

    for (int kb = 0; kb <= qb; ++kb) {
        cp_wait<1>();
        __syncthreads();

        float S[16][4];
        #pragma unroll
        for (int i = 0; i < 16; ++i)
            #pragma unroll
            for (int j = 0; j < 4; ++j) S[i][j] = 0.f;

        #pragma unroll
        for (int ks = 0; ks < 8; ++ks) {
            uint32_t qf[4];
            {
                int r = wid * 16 + (lane & 15);
                int c = ks * 16 + (lane >> 4) * 8;
                ldsm4(qf, s2u(&sQh[r * FL_PITCH + c]));
            }
            #pragma unroll
            for (int nt = 0; nt < 16; ++nt) {
                uint32_t bh[2], bl[2];
                int r = nt * 8 + (lane & 7);
                int c = ks * 16 + ((lane >> 3) & 1) * 8;
                ldsm2(bh, s2u(&sKh[r * FL_PITCH + c]));
                ldsm2(bl, s2u(&sKl[r * FL_PITCH + c]));
                mma16816(S[nt], qf, bh);
                mma16816(S[nt], qf, bl);
            }
        }
        __syncthreads();
        if (kb < qb) { loadK(kb + 1); cp_commit(); }

        bool diag = (kb == qb);
        #pragma unroll
        for (int nt = 0; nt < 16; ++nt)
            #pragma unroll
            for (int j = 0; j < 4; ++j) {
                float v = S[nt][j] * scale;
                if (diag) {
                    int n = nt * 8 + tg * 2 + (j & 1);
                    int m = wid * 16 + g + ((j >> 1) ? 8 : 0);
                    if (n > m) v = -INFINITY;
                }
                S[nt][j] = v;
            }

        float mx0 = -INFINITY, mx1 = -INFINITY;
        #pragma unroll
        for (int nt = 0; nt < 16; ++nt) {
            mx0 = fmaxf(mx0, fmaxf(S[nt][0], S[nt][1]));
            mx1 = fmaxf(mx1, fmaxf(S[nt][2], S[nt][3]));
        }
        mx0 = fmaxf(mx0, __shfl_xor_sync(0xffffffffu, mx0, 1));
        mx0 = fmaxf(mx0, __shfl_xor_sync(0xffffffffu, mx0, 2));
        mx1 = fmaxf(mx1, __shfl_xor_sync(0xffffffffu, mx1, 1));
        mx1 = fmaxf(mx1, __shfl_xor_sync(0xffffffffu, mx1, 2));

        float mn0 = fmaxf(mrun0, mx0);
        float mn1 = fmaxf(mrun1, mx1);
        float al0 = expf(mrun0 - mn0);
        float al1 = expf(mrun1 - mn1);
        mrun0 = mn0; mrun1 = mn1;

        float ls0 = 0.f, ls1 = 0.f;
        #pragma unroll
        for (int nt = 0; nt < 16; ++nt) {
            float e0 = expf(S[nt][0] - mn0);
            float e1 = expf(S[nt][1] - mn0);
            float e2 = expf(S[nt][2] - mn1);
            float e3 = expf(S[nt][3] - mn1);
            S[nt][0] = e0; S[nt][1] = e1; S[nt][2] = e2; S[nt][3] = e3;
            ls0 += e0 + e1;
            ls1 += e2 + e3;
        }
        lrun0 = lrun0 * al0 + ls0;
        lrun1 = lrun1 * al1 + ls1;

        #pragma unroll
        for (int nt = 0; nt < 16; ++nt) {
            accO[nt][0] *= al0; accO[nt][1] *= al0;
            accO[nt][2] *= al1; accO[nt][3] *= al1;
        }

        if (kb < qb) cp_wait<1>(); else cp_wait<0>();
        __syncthreads();

        #pragma unroll
        for (int kk = 0; kk < 8; ++kk) {
            uint32_t ph[4];
            ph[0] = packb2(S[2 * kk][0],     S[2 * kk][1]);
            ph[1] = packb2(S[2 * kk][2],     S[2 * kk][3]);
            ph[2] = packb2(S[2 * kk + 1][0], S[2 * kk + 1][1]);
            ph[3] = packb2(S[2 * kk + 1][2], S[2 * kk + 1][3]);
            #pragma unroll
            for (int ndt = 0; ndt < 16; ++ndt) {
                uint32_t vh2[2], vl2[2];
                int rr = kk * 16 + (lane & 15);
                int cc = ndt * 8;
                ldsm2t(vh2, s2u(&sVh[rr * FL_PITCH + cc]));
                ldsm2t(vl2, s2u(&sVl[rr * FL_PITCH + cc]));
                mma16816(accO[ndt], ph, vh2);
                mma16816(accO[ndt], ph, vl2);
            }
        }
        __syncthreads();
        if (kb < qb) { loadV(kb + 1); cp_commit(); }
    }

    lrun0 += __shfl_xor_sync(0xffffffffu, lrun0, 1);
    lrun0 += __shfl_xor_sync(0xffffffffu, lrun0, 2);
    lrun1 += __shfl_xor_sync(0xffffffffu, lrun1, 1);
    lrun1 += __shfl_xor_sync(0xffffffffu, lrun1, 2);
    float inv0 = 1.0f / lrun0;
    float inv1 = 1.0f / lrun1;

    size_t obase = (size_t)z * TT * DHD;
    #pragma unroll
    for (int ndt = 0; ndt < 16; ++ndt)
        #pragma unroll
        for (int j = 0; j < 4; ++j) {
            int m = row0 + wid * 16 + g + ((j >> 1) ? 8 : 0);
            int n = ndt * 8 + tg * 2 + (j & 1);
            float v = accO[ndt][j] * ((j >> 1) ? inv1 : inv0);
            size_t idx = obase + (size_t)m * DHD + n;
            split2(v, &aoh[idx], &aol[idx]);
        }
}

// ---------------- host ----------------
#define SYMADDR(var, sym) cudaGetSymbolAddress((void**)&var, sym)

extern "C" void kernel_launch(void* const* d_in, const int* in_sizes, int n_in,
                              void* d_out, int out_size) {
    const float* x   = (const float*)d_in[0];
    const float* l3  = (const float*)d_in[1];
    const float* wq  = (const float*)d_in[2];
    const float* wk  = (const float*)d_in[3];
    const float* wv  = (const float*)d_in[4];
    const float* wo  = (const float*)d_in[5];
    const float* rw1 = (const float*)d_in[6];
    const float* rb1 = (const float*)d_in[7];
    const float* rw2 = (const float*)d_in[8];
    const float* rb2 = (const float*)d_in[9];

    float* out     = (float*)d_out;
    float* kh_out  = out    + (size_t)BB * TT * DD;
    float* vh_out  = kh_out + (size_t)BB * TT * DD;
    float* lam_out = vh_out + (size_t)BB * TT * DD;

    float *carryA, *carryB, *lampart;
    SYMADDR(carryA, g_carryA); SYMADDR(carryB, g_carryB);
    SYMADDR(lampart, g_lampart);

    __nv_bfloat16 *xs_h,*xs_l, *wqs_h,*wqs_l, *wks_h,*wks_l, *wvs_h,*wvs_l,
                  *wos_h,*wos_l, *rw1s_h,*rw1s_l, *qs_h, *fs_h,*fs_l,
                  *khs_h,*khs_l, *vhs_h,*vhs_l, *aos_h,*aos_l;
    SYMADDR(xs_h, g_xs_h);     SYMADDR(xs_l, g_xs_l);
    SYMADDR(wqs_h, g_wqs_h);   SYMADDR(wqs_l, g_wqs_l);
    SYMADDR(wks_h, g_wks_h);   SYMADDR(wks_l, g_wks_l);
    SYMADDR(wvs_h, g_wvs_h);   SYMADDR(wvs_l, g_wvs_l);
    SYMADDR(wos_h, g_wos_h);   SYMADDR(wos_l, g_wos_l);
    SYMADDR(rw1s_h, g_rw1s_h); SYMADDR(rw1s_l, g_rw1s_l);
    SYMADDR(qs_h, g_qs_h);
    SYMADDR(fs_h, g_fs_h);     SYMADDR(fs_l, g_fs_l);
    SYMADDR(khs_h, g_khs_h);   SYMADDR(khs_l, g_khs_l);
    SYMADDR(vhs_h, g_vhs_h);   SYMADDR(vhs_l, g_vhs_l);
    SYMADDR(aos_h, g_aos_h);   SYMADDR(aos_l, g_aos_l);

    const int M = BB * TT;
    const float scale = 1.0f / sqrtf((float)DHD);
    const int NW4 = (int)((size_t)DD * DD / 4);

    cudaFuncSetAttribute(mma_gemm<M_Q>,   cudaFuncAttributeMaxDynamicSharedMemorySize, GEMM_SMEM);
    cudaFuncSetAttribute(mma_gemm<M_HDN>, cudaFuncAttributeMaxDynamicSharedMemorySize, GEMM_SMEM);
    cudaFuncSetAttribute(mma_gemm<M_KV2>, cudaFuncAttributeMaxDynamicSharedMemorySize, GEMM_SMEM);
    cudaFuncSetAttribute(mma_gemm<M_OUT>, cudaFuncAttributeMaxDynamicSharedMemorySize, GEMM_SMEM);
    cudaFuncSetAttribute(flash_kernel,    cudaFuncAttributeMaxDynamicSharedMemorySize, FLASH_SMEM);

    // weight splits (vectorized x4)
    split4_v4_kernel<<<(NW4 + 255) / 256, 256>>>(
        (const float4*)wq, (const float4*)wk, (const float4*)wv, (const float4*)wo,
        (uint2*)wqs_h, (uint2*)wqs_l, (uint2*)wks_h, (uint2*)wks_l,
        (uint2*)wvs_h, (uint2*)wvs_l, (uint2*)wos_h, (uint2*)wos_l, NW4);
    split_v4_kernel<<<(NW4 / 2 + 255) / 256, 256>>>(
        (const float4*)rw1, (uint2*)rw1s_h, (uint2*)rw1s_l, NW4 / 2);

    // EMA chunk scan fused with x split; then scalar carries (16 blocks)
    ema_chunk_split_v4<<<(BB * NC * D4 + 255) / 256, 256>>>(
        (const float4*)x, (float4*)carryA, (uint2*)xs_h, (uint2*)xs_l);
    ema_carry_s<<<(BB * DD + 255) / 256, 256>>>(carryA, carryB);

    // q = x @ wq^T  (hi-only output)
    mma_gemm<M_Q><<<dim3(DD / BN, M / BM), 256, GEMM_SMEM>>>(
        xs_h, xs_l, wqs_h, wqs_l, nullptr, nullptr, nullptr, nullptr, nullptr,
        nullptr, nullptr, qs_h, nullptr, nullptr, nullptr, M, DD, DD, DD, DD);

    // hdn + router partials fused (2-term: A hi only)
    mma_gemm<M_HDN><<<dim3(DHALF / BN, M / BM), 256, GEMM_SMEM>>>(
        qs_h, nullptr, rw1s_h, rw1s_l, nullptr, nullptr, rb1, rw2, lampart,
        nullptr, nullptr, nullptr, nullptr, nullptr, nullptr, M, DHALF, DD, DD, DD);

    // lam = softmax(sum partials + rb2)
    router_final<<<(M + 255) / 256, 256>>>(lampart, rb2, lam_out);

    // EMA rescan + fuse + split (single pass)
    ema_fuse_v4<<<(BB * NC * D4 + 255) / 256, 256>>>(
        (const float4*)x, (const float4*)carryB, (const float4*)l3, lam_out,
        (uint2*)fs_h, (uint2*)fs_l);

    // kh + vh in ONE launch
    mma_gemm<M_KV2><<<dim3(2 * DD / BN, M / BM), 256, GEMM_SMEM>>>(
        fs_h, fs_l, wks_h, wks_l, wvs_h, wvs_l, nullptr, nullptr, nullptr,
        kh_out, vh_out, khs_h, khs_l, vhs_h, vhs_l, M, DD, DD, DD, DD);

    // flash attention
    flash_kernel<<<dim3(TT / 128, BB * HH), 256, FLASH_SMEM>>>(
        qs_h, khs_h, khs_l, vhs_h, vhs_l, aos_h, aos_l, scale);

    // out = concat_heads(ao) @ wo^T
    mma_gemm<M_OUT><<<dim3(DD / BN, M / BM), 256, GEMM_SMEM>>>(
        aos_h, aos_l, wos_h, wos_l, nullptr, nullptr, nullptr, nullptr, nullptr,
        out, nullptr, nullptr, nullptr, nullptr, nullptr, M, DD, DD, DD, DD);
}